// round 9
// baseline (speedup 1.0000x reference)
#include <cuda_runtime.h>
#include <math.h>
#include <stdint.h>

#define B_    4096
#define MROWS (B_ * 128)   // 524288

// ---------------- global scratch ----------------
__device__ float g_h[(size_t)MROWS * 128];
__device__ float g_qkv[(size_t)MROWS * 384];
__device__ float g_attn[(size_t)MROWS * 128];
__device__ float g_ch1[(size_t)MROWS * 64];
__device__ float g_comb[(size_t)B_ * 256];
__device__ float g_mw[(size_t)B_ * 4];
__device__ float g_base[(size_t)B_ * 512];
__device__ float g_sw1p[256 * 512];   // folded student weight [256,512] row-major

typedef unsigned long long u64t;

__device__ __forceinline__ float siluf(float x) { return x / (1.f + __expf(-x)); }
__device__ __forceinline__ float tanh_fast(float x) { return 1.f - 2.f / (__expf(2.f * x) + 1.f); }
__device__ __forceinline__ void fma2(u64t& d, u64t a, u64t b) {
    asm("fma.rn.f32x2 %0, %1, %2, %0;" : "+l"(d) : "l"(a), "l"(b));
}
__device__ __forceinline__ u64t pk2(float x, float y) {
    u64t r; asm("mov.b64 %0, {%1, %2};" : "=l"(r) : "f"(x), "f"(y)); return r;
}
__device__ __forceinline__ float2 up2(u64t v) {
    float2 r; asm("mov.b64 {%0, %1}, %2;" : "=f"(r.x), "=f"(r.y) : "l"(v)); return r;
}
__device__ __forceinline__ uint32_t smem_u32(const void* p) {
    uint32_t a;
    asm("{ .reg .u64 t; cvta.to.shared.u64 t, %1; cvt.u32.u64 %0, t; }" : "=r"(a) : "l"(p));
    return a;
}

// ---- cp.async ----
__device__ __forceinline__ void cp16(uint32_t dst, const void* src) {
    asm volatile("cp.async.ca.shared.global [%0], [%1], 16;" :: "r"(dst), "l"(src));
}
__device__ __forceinline__ void cp_commit() { asm volatile("cp.async.commit_group;" ::: "memory"); }
template <int N>
__device__ __forceinline__ void cp_wait() { asm volatile("cp.async.wait_group %0;" :: "n"(N) : "memory"); }

// ---- tf32 mma.sync m16n8k8 ----
__device__ __forceinline__ void mma8(float* c, const uint32_t* a, uint32_t b0, uint32_t b1) {
    asm volatile(
        "mma.sync.aligned.m16n8k8.row.col.f32.tf32.tf32.f32 "
        "{%0,%1,%2,%3}, {%4,%5,%6,%7}, {%8,%9}, {%0,%1,%2,%3};"
        : "+f"(c[0]), "+f"(c[1]), "+f"(c[2]), "+f"(c[3])
        : "r"(a[0]), "r"(a[1]), "r"(a[2]), "r"(a[3]), "r"(b0), "r"(b1));
}

// split fp32 into tf32 hi + tf32 lo (3xTF32 compensation)
__device__ __forceinline__ void split_tf32(uint32_t raw, uint32_t& hi, uint32_t& lo) {
    float x = __uint_as_float(raw);
    float h, l;
    asm("cvt.rna.tf32.f32 %0, %1;" : "=f"(h) : "f"(x));
    float r = x - h;
    asm("cvt.rna.tf32.f32 %0, %1;" : "=f"(l) : "f"(r));
    hi = __float_as_uint(h);
    lo = __float_as_uint(l);
}

// ---------------- tf32 tensor GEMM (3xTF32, 256 threads, B pre-split in smem) ---------
// C[bm:bm+128, bn:bn+128] = A[128,Ktot] @ W[Ktot, ldb](cols bn..) + epilogue
// MODE: 0 bias, 1 relu, 2 residual+LayerNorm (N==128, grid.x==1, ldc==128), 3 silu
#define ASZ  18432                 // 128 * 36 floats
#define BSZ2 33792                 // 32 * 132 u64 (hi,lo)
#define TG_SMEM (2 * ASZ + 2 * BSZ2)   // 104448
template <int MODE>
__global__ void __launch_bounds__(256, 2) tgemm(const float* __restrict__ A, int lda,
                                                const float* __restrict__ W, int ldb, int Ktot,
                                                const float* __restrict__ bias,
                                                const float* __restrict__ res,
                                                const float* __restrict__ gma,
                                                const float* __restrict__ bta,
                                                float* __restrict__ C, int ldc) {
    extern __shared__ char dsm[];
    const uint32_t sbase = smem_u32(dsm);
    const int t = threadIdx.x;
    const int w = t >> 5, lane = t & 31;
    const int g = lane >> 2, t4 = lane & 3;
    const int bn = blockIdx.x * 128, bm = blockIdx.y * 128;
    const int wr = w * 16;

    float acc[16][4];
#pragma unroll
    for (int j = 0; j < 16; j++)
#pragma unroll
        for (int q = 0; q < 4; q++) acc[j][q] = 0.f;

    const int P = Ktot >> 5;
    const int brow = t >> 5;          // B staging: warp w loads row w (+8, +16, +24)
    const int bc4 = (t & 31) * 4;

    float4 breg[4];
    // ---- prologue: stage tile 0 ----
    {
#pragma unroll
        for (int i = 0; i < 4; i++) {
            int idx = t + i * 256;
            int row = idx >> 3, c4 = (idx & 7) * 4;
            cp16(sbase + (uint32_t)(row * 36 + c4) * 4u, A + (size_t)(bm + row) * lda + c4);
        }
        cp_commit();
#pragma unroll
        for (int i = 0; i < 4; i++)
            breg[i] = *(const float4*)(W + (size_t)(brow + i * 8) * ldb + bn + bc4);
        uint2* Bs = (uint2*)(dsm + 2 * ASZ);
#pragma unroll
        for (int i = 0; i < 4; i++) {
            uint2 e0, e1, e2, e3;
            split_tf32(__float_as_uint(breg[i].x), e0.x, e0.y);
            split_tf32(__float_as_uint(breg[i].y), e1.x, e1.y);
            split_tf32(__float_as_uint(breg[i].z), e2.x, e2.y);
            split_tf32(__float_as_uint(breg[i].w), e3.x, e3.y);
            uint2* dst = Bs + (brow + i * 8) * 132 + bc4;
            *(uint4*)(dst + 0) = make_uint4(e0.x, e0.y, e1.x, e1.y);
            *(uint4*)(dst + 2) = make_uint4(e2.x, e2.y, e3.x, e3.y);
        }
    }

    for (int p = 0; p < P; p++) {
        cp_wait<0>();
        __syncthreads();
        const bool more = (p + 1 < P);
        if (more) {
            const int buf = (p + 1) & 1;
            const int kof = (p + 1) * 32;
#pragma unroll
            for (int i = 0; i < 4; i++) {
                int idx = t + i * 256;
                int row = idx >> 3, c4 = (idx & 7) * 4;
                cp16(sbase + (uint32_t)(buf * ASZ + (row * 36 + c4) * 4), 
                     A + (size_t)(bm + row) * lda + kof + c4);
            }
            cp_commit();
#pragma unroll
            for (int i = 0; i < 4; i++)
                breg[i] = *(const float4*)(W + (size_t)(kof + brow + i * 8) * ldb + bn + bc4);
        }
        // ---- compute from buf p&1 ----
        const uint32_t* Asu = (const uint32_t*)(dsm + (p & 1) * ASZ);
        const uint2* Bsu = (const uint2*)(dsm + 2 * ASZ + (p & 1) * BSZ2);
#pragma unroll
        for (int ks = 0; ks < 4; ks++) {
            const int k0 = ks * 8;
            const int r = wr + g;
            uint32_t ah[4], al[4];
            split_tf32(Asu[(r) * 36 + k0 + t4],         ah[0], al[0]);
            split_tf32(Asu[(r + 8) * 36 + k0 + t4],     ah[1], al[1]);
            split_tf32(Asu[(r) * 36 + k0 + t4 + 4],     ah[2], al[2]);
            split_tf32(Asu[(r + 8) * 36 + k0 + t4 + 4], ah[3], al[3]);
#pragma unroll
            for (int j = 0; j < 16; j++) {
                uint2 b0 = Bsu[(k0 + t4) * 132 + j * 8 + g];
                uint2 b1 = Bsu[(k0 + t4 + 4) * 132 + j * 8 + g];
                mma8(acc[j], ah, b0.x, b1.x);
                mma8(acc[j], al, b0.x, b1.x);
                mma8(acc[j], ah, b0.y, b1.y);
            }
        }
        if (more) {
            const int buf = (p + 1) & 1;
            uint2* Bs = (uint2*)(dsm + 2 * ASZ + buf * BSZ2);
#pragma unroll
            for (int i = 0; i < 4; i++) {
                uint2 e0, e1, e2, e3;
                split_tf32(__float_as_uint(breg[i].x), e0.x, e0.y);
                split_tf32(__float_as_uint(breg[i].y), e1.x, e1.y);
                split_tf32(__float_as_uint(breg[i].z), e2.x, e2.y);
                split_tf32(__float_as_uint(breg[i].w), e3.x, e3.y);
                uint2* dst = Bs + (brow + i * 8) * 132 + bc4;
                *(uint4*)(dst + 0) = make_uint4(e0.x, e0.y, e1.x, e1.y);
                *(uint4*)(dst + 2) = make_uint4(e2.x, e2.y, e3.x, e3.y);
            }
        }
    }

    // ---------------- epilogue ----------------
    float2 bias2[16];
#pragma unroll
    for (int j = 0; j < 16; j++) bias2[j] = *(const float2*)(bias + bn + j * 8 + 2 * t4);

    if (MODE == 2) {
#pragma unroll
        for (int h = 0; h < 2; h++) {
            const int row = bm + wr + h * 8 + g;
            const float* rp = res + (size_t)row * 128 + 2 * t4;
            float sum = 0.f;
#pragma unroll
            for (int j = 0; j < 16; j++) {
                float2 rv = *(const float2*)(rp + j * 8);
                float v0 = acc[j][2 * h] + bias2[j].x + rv.x;
                float v1 = acc[j][2 * h + 1] + bias2[j].y + rv.y;
                acc[j][2 * h] = v0;
                acc[j][2 * h + 1] = v1;
                sum += v0 + v1;
            }
            sum += __shfl_xor_sync(0xffffffffu, sum, 1);
            sum += __shfl_xor_sync(0xffffffffu, sum, 2);
            const float mean = sum * (1.f / 128.f);
            float var = 0.f;
#pragma unroll
            for (int j = 0; j < 16; j++) {
                float v0 = acc[j][2 * h] - mean;
                float v1 = acc[j][2 * h + 1] - mean;
                acc[j][2 * h] = v0;
                acc[j][2 * h + 1] = v1;
                var += v0 * v0 + v1 * v1;
            }
            var += __shfl_xor_sync(0xffffffffu, var, 1);
            var += __shfl_xor_sync(0xffffffffu, var, 2);
            const float rs = rsqrtf(var * (1.f / 128.f) + 1e-5f);
            float* cp = C + (size_t)row * 128 + 2 * t4;
#pragma unroll
            for (int j = 0; j < 16; j++) {
                float2 gv = *(const float2*)(gma + j * 8 + 2 * t4);
                float2 tv = *(const float2*)(bta + j * 8 + 2 * t4);
                float2 o;
                o.x = fmaf(gv.x, acc[j][2 * h] * rs, tv.x);
                o.y = fmaf(gv.y, acc[j][2 * h + 1] * rs, tv.y);
                *(float2*)(cp + j * 8) = o;
            }
        }
    } else {
#pragma unroll
        for (int h = 0; h < 2; h++) {
            const int row = bm + wr + h * 8 + g;
            float* cp = C + (size_t)row * ldc + bn + 2 * t4;
#pragma unroll
            for (int j = 0; j < 16; j++) {
                float2 o;
                o.x = acc[j][2 * h] + bias2[j].x;
                o.y = acc[j][2 * h + 1] + bias2[j].y;
                if (MODE == 1) { o.x = fmaxf(o.x, 0.f); o.y = fmaxf(o.y, 0.f); }
                if (MODE == 3) { o.x = siluf(o.x); o.y = siluf(o.y); }
                *(float2*)(cp + j * 8) = o;
            }
        }
    }
}

// ---------------- time embedding ----------------
__global__ void __launch_bounds__(256) time_kernel(const int* __restrict__ ts,
                                                   const float* __restrict__ w1,
                                                   const float* __restrict__ b1,
                                                   const float* __restrict__ w2,
                                                   const float* __restrict__ b2) {
    __shared__ float te[128];
    __shared__ float hid[256];
    const int b = blockIdx.x, t = threadIdx.x;
    const float tf = (float)ts[b];
    if (t < 128) {
        int i = t & 63;
        float freq = expf(-0.14391156831212787f * (float)i);
        float arg = tf * freq;
        te[t] = (t < 64) ? cosf(arg) : sinf(arg);
    }
    __syncthreads();
    float a = b1[t];
    for (int i = 0; i < 128; i++) a = fmaf(te[i], w1[i * 256 + t], a);
    hid[t] = siluf(a);
    __syncthreads();
    if (t < 128) {
        float a2 = b2[t];
        for (int i = 0; i < 256; i++) a2 = fmaf(hid[i], w2[i * 128 + t], a2);
        g_comb[(size_t)b * 256 + t] = a2;
    }
}

// ---------------- cond layer1 ----------------
__global__ void __launch_bounds__(256) condh1_kernel(const float* __restrict__ cond,
                                                     const float* __restrict__ w1,
                                                     const float* __restrict__ b1) {
    const size_t row = (size_t)blockIdx.x * 32 + (threadIdx.x >> 3);
    const int dg = threadIdx.x & 7;
    const float* cp = cond + row * 6;
    float c0 = cp[0], c1 = cp[1], c2 = cp[2], c3 = cp[3], c4 = cp[4], c5 = cp[5];
    float o[8];
#pragma unroll
    for (int j = 0; j < 8; j++) {
        int dd = dg * 8 + j;
        float a = b1[dd];
        a = fmaf(c0, w1[0 * 64 + dd], a);
        a = fmaf(c1, w1[1 * 64 + dd], a);
        a = fmaf(c2, w1[2 * 64 + dd], a);
        a = fmaf(c3, w1[3 * 64 + dd], a);
        a = fmaf(c4, w1[4 * 64 + dd], a);
        a = fmaf(c5, w1[5 * 64 + dd], a);
        o[j] = siluf(a);
    }
    float4 v0, v1;
    v0.x = o[0]; v0.y = o[1]; v0.z = o[2]; v0.w = o[3];
    v1.x = o[4]; v1.y = o[5]; v1.z = o[6]; v1.w = o[7];
    *(float4*)(g_ch1 + row * 64 + dg * 8) = v0;
    *(float4*)(g_ch1 + row * 64 + dg * 8 + 4) = v1;
}

// ---------------- attention (fp32, f32x2) ----------------
#define ATTN_SMEM ((8192 + 128 * 129) * 4)
__global__ void __launch_bounds__(128) attn_kernel() {
    extern __shared__ float smem[];
    float (*ks)[32] = (float(*)[32])smem;
    float (*vs)[32] = (float(*)[32])(smem + 4096);
    float (*sc)[129] = (float(*)[129])(smem + 8192);
    const int b = blockIdx.x >> 2;
    const int hd = blockIdx.x & 3;
    const int t = threadIdx.x;
    const float* rowp = g_qkv + ((size_t)b * 128 + t) * 384;
#pragma unroll
    for (int c = 0; c < 8; c++)
        *(float4*)&ks[t][c * 4] = *(const float4*)(rowp + 128 + hd * 32 + c * 4);
#pragma unroll
    for (int c = 0; c < 8; c++)
        *(float4*)&vs[t][c * 4] = *(const float4*)(rowp + 256 + hd * 32 + c * 4);
    u64t q2[16];
#pragma unroll
    for (int c = 0; c < 8; c++) {
        ulonglong2 qv = *(const ulonglong2*)(rowp + hd * 32 + c * 4);
        q2[2 * c] = qv.x;
        q2[2 * c + 1] = qv.y;
    }
    __syncthreads();
    const float scale = 0.17677669529663687f;
    float m = -1e30f;
    for (int j = 0; j < 128; j++) {
        u64t d2 = 0ULL;
        const ulonglong2* kp = (const ulonglong2*)&ks[j][0];
#pragma unroll
        for (int c = 0; c < 8; c++) {
            ulonglong2 kv = kp[c];
            fma2(d2, q2[2 * c], kv.x);
            fma2(d2, q2[2 * c + 1], kv.y);
        }
        float2 dp = up2(d2);
        float s = (dp.x + dp.y) * scale;
        sc[t][j] = s;
        m = fmaxf(m, s);
    }
    float l = 0.f;
    u64t acc2[16];
#pragma unroll
    for (int i = 0; i < 16; i++) acc2[i] = 0ULL;
    for (int j = 0; j < 128; j++) {
        float e = __expf(sc[t][j] - m);
        l += e;
        u64t e2 = pk2(e, e);
        const ulonglong2* vp = (const ulonglong2*)&vs[j][0];
#pragma unroll
        for (int c = 0; c < 8; c++) {
            ulonglong2 vv = vp[c];
            fma2(acc2[2 * c], e2, vv.x);
            fma2(acc2[2 * c + 1], e2, vv.y);
        }
    }
    const float inv = 1.f / l;
    float* op = g_attn + ((size_t)b * 128 + t) * 128 + hd * 32;
#pragma unroll
    for (int c = 0; c < 16; c++) {
        float2 p = up2(acc2[c]);
        p.x *= inv;
        p.y *= inv;
        *(float2*)(op + 2 * c) = p;
    }
}

// ---------------- mean pool ----------------
__global__ void __launch_bounds__(128) pool_kernel() {
    const int b = blockIdx.x, d = threadIdx.x;
    const float* p = g_h + (size_t)b * 128 * 128 + d;
    float s = 0.f;
    for (int j = 0; j < 128; j++) s += p[j * 128];
    g_comb[(size_t)b * 256 + 128 + d] = s * (1.f / 128.f);
}

// ---------------- mixture weights ----------------
__global__ void __launch_bounds__(128) mw_kernel(const float* __restrict__ w1,
                                                 const float* __restrict__ b1,
                                                 const float* __restrict__ w2,
                                                 const float* __restrict__ b2) {
    __shared__ float scm[256];
    __shared__ float hid[128];
    __shared__ float lg[4];
    const int b = blockIdx.x, t = threadIdx.x;
    scm[t] = g_comb[(size_t)b * 256 + t];
    scm[128 + t] = g_comb[(size_t)b * 256 + 128 + t];
    __syncthreads();
    float a = b1[t];
    for (int i = 0; i < 256; i++) a = fmaf(scm[i], w1[i * 128 + t], a);
    hid[t] = siluf(a);
    __syncthreads();
    if (t < 4) {
        float a2 = b2[t];
        for (int j = 0; j < 128; j++) a2 = fmaf(hid[j], w2[j * 4 + t], a2);
        lg[t] = a2;
    }
    __syncthreads();
    if (t == 0) {
        float mm = fmaxf(fmaxf(lg[0], lg[1]), fmaxf(lg[2], lg[3]));
        float e0 = __expf(lg[0] - mm), e1 = __expf(lg[1] - mm);
        float e2 = __expf(lg[2] - mm), e3 = __expf(lg[3] - mm);
        float inv = 1.f / (e0 + e1 + e2 + e3);
        g_mw[(size_t)b * 4 + 0] = e0 * inv;
        g_mw[(size_t)b * 4 + 1] = e1 * inv;
        g_mw[(size_t)b * 4 + 2] = e2 * inv;
        g_mw[(size_t)b * 4 + 3] = e3 * inv;
    }
}

// ---------------- student fold pack (plain row-major [256,512]) ----------------
__global__ void __launch_bounds__(256) packsw1(const float* __restrict__ sw1) {
    int idx = blockIdx.x * 256 + threadIdx.x;  // < 256*512
    int i = idx >> 9;
    int n = idx & 511;
    g_sw1p[idx] = sw1[((size_t)(n >> 7) * 258 + 2 + i) * 128 + (n & 127)];
}

// ---------------- students ----------------
__global__ void __launch_bounds__(128) student_kernel(const float* __restrict__ x,
                                                      const float* __restrict__ sw1,
                                                      const float* __restrict__ sw2,
                                                      const float* __restrict__ sb2,
                                                      float* __restrict__ out) {
    __shared__ float sb[512], w0[512], w1s[512], s2a[512], s2b[512];
    __shared__ float smw[4], sbias2[8];
    const int b = blockIdx.x, t = threadIdx.x;
    for (int i = t; i < 512; i += 128) {
        sb[i] = g_base[(size_t)b * 512 + i];
        int k = i >> 7, j = i & 127;
        w0[i] = sw1[((size_t)k * 258 + 0) * 128 + j];
        w1s[i] = sw1[((size_t)k * 258 + 1) * 128 + j];
        s2a[i] = sw2[i * 2 + 0];
        s2b[i] = sw2[i * 2 + 1];
    }
    if (t < 4) smw[t] = g_mw[(size_t)b * 4 + t];
    if (t < 8) sbias2[t] = sb2[t];
    __syncthreads();
    const float x0 = x[(size_t)b * 256 + t];
    const float x1 = x[(size_t)b * 256 + 128 + t];
    float o0 = 0.f, o1 = 0.f;
#pragma unroll
    for (int k = 0; k < 4; k++) {
        float a0 = 0.f, a1 = 0.f;
        for (int j = 0; j < 128; j++) {
            int idx = k * 128 + j;
            float hv = tanh_fast(fmaf(x1, w1s[idx], fmaf(x0, w0[idx], sb[idx])));
            a0 = fmaf(hv, s2a[idx], a0);
            a1 = fmaf(hv, s2b[idx], a1);
        }
        float wk = smw[k];
        o0 = fmaf(wk, a0 + sbias2[k * 2 + 0], o0);
        o1 = fmaf(wk, a1 + sbias2[k * 2 + 1], o1);
    }
    out[(size_t)b * 256 + t] = o0;
    out[(size_t)b * 256 + 128 + t] = o1;
}

// ---------------- launcher ----------------
extern "C" void kernel_launch(void* const* d_in, const int* in_sizes, int n_in,
                              void* d_out, int out_size) {
    const float* x    = (const float*)d_in[0];
    const int*   ts   = (const int*)d_in[1];
    const float* cond = (const float*)d_in[2];
    const float* t_w1 = (const float*)d_in[3];
    const float* t_b1 = (const float*)d_in[4];
    const float* t_w2 = (const float*)d_in[5];
    const float* t_b2 = (const float*)d_in[6];
    const float* c_w1 = (const float*)d_in[7];
    const float* c_b1 = (const float*)d_in[8];
    const float* c_w2 = (const float*)d_in[9];
    const float* c_b2 = (const float*)d_in[10];
    const float* wqkv = (const float*)d_in[11];
    const float* bqkv = (const float*)d_in[12];
    const float* wo   = (const float*)d_in[13];
    const float* bo   = (const float*)d_in[14];
    const float* ln1g = (const float*)d_in[15];
    const float* ln1b = (const float*)d_in[16];
    const float* ffw1 = (const float*)d_in[17];
    const float* ffb1 = (const float*)d_in[18];
    const float* ffw2 = (const float*)d_in[19];
    const float* ffb2 = (const float*)d_in[20];
    const float* ln2g = (const float*)d_in[21];
    const float* ln2b = (const float*)d_in[22];
    const float* mww1 = (const float*)d_in[23];
    const float* mwb1 = (const float*)d_in[24];
    const float* mww2 = (const float*)d_in[25];
    const float* mwb2 = (const float*)d_in[26];
    const float* sw1  = (const float*)d_in[27];
    const float* sb1  = (const float*)d_in[28];
    const float* sw2  = (const float*)d_in[29];
    const float* sb2  = (const float*)d_in[30];
    float* out = (float*)d_out;

    float *gh, *gqkv, *gattn, *gch1, *gcomb, *gbase, *gsw1p;
    cudaGetSymbolAddress((void**)&gh, g_h);
    cudaGetSymbolAddress((void**)&gqkv, g_qkv);
    cudaGetSymbolAddress((void**)&gattn, g_attn);
    cudaGetSymbolAddress((void**)&gch1, g_ch1);
    cudaGetSymbolAddress((void**)&gcomb, g_comb);
    cudaGetSymbolAddress((void**)&gbase, g_base);
    cudaGetSymbolAddress((void**)&gsw1p, g_sw1p);

    cudaFuncSetAttribute(attn_kernel, cudaFuncAttributeMaxDynamicSharedMemorySize, ATTN_SMEM);
    cudaFuncSetAttribute(tgemm<0>, cudaFuncAttributeMaxDynamicSharedMemorySize, TG_SMEM);
    cudaFuncSetAttribute(tgemm<1>, cudaFuncAttributeMaxDynamicSharedMemorySize, TG_SMEM);
    cudaFuncSetAttribute(tgemm<2>, cudaFuncAttributeMaxDynamicSharedMemorySize, TG_SMEM);
    cudaFuncSetAttribute(tgemm<3>, cudaFuncAttributeMaxDynamicSharedMemorySize, TG_SMEM);

    time_kernel<<<B_, 256>>>(ts, t_w1, t_b1, t_w2, t_b2);
    condh1_kernel<<<MROWS / 32, 256>>>(cond, c_w1, c_b1);
    packsw1<<<(256 * 512) / 256, 256>>>(sw1);
    // cond layer2: silu(g_ch1 @ c_w2 + b)  [M,64]@[64,128]
    tgemm<3><<<dim3(1, MROWS / 128), 256, TG_SMEM>>>(gch1, 64, c_w2, 128, 64, c_b2,
                                                     nullptr, nullptr, nullptr, gh, 128);
    for (int l = 0; l < 2; l++) {
        // qkv
        tgemm<0><<<dim3(3, MROWS / 128), 256, TG_SMEM>>>(gh, 128, wqkv + (size_t)l * 49152, 384,
                                                         128, bqkv + l * 384, nullptr, nullptr,
                                                         nullptr, gqkv, 384);
        attn_kernel<<<B_ * 4, 128, ATTN_SMEM>>>();
        // o-proj + res + LN
        tgemm<2><<<dim3(1, MROWS / 128), 256, TG_SMEM>>>(gattn, 128, wo + (size_t)l * 16384, 128,
                                                         128, bo + l * 128, gh, ln1g + l * 128,
                                                         ln1b + l * 128, gh, 128);
        // ffn1 relu
        tgemm<1><<<dim3(2, MROWS / 128), 256, TG_SMEM>>>(gh, 128, ffw1 + (size_t)l * 32768, 256,
                                                         128, ffb1 + l * 256, nullptr, nullptr,
                                                         nullptr, gqkv, 256);
        // ffn2 + res + LN
        tgemm<2><<<dim3(1, MROWS / 128), 256, TG_SMEM>>>(gqkv, 256, ffw2 + (size_t)l * 32768, 128,
                                                         256, ffb2 + l * 128, gh, ln2g + l * 128,
                                                         ln2b + l * 128, gh, 128);
    }
    pool_kernel<<<B_, 128>>>();
    mw_kernel<<<B_, 128>>>(mww1, mwb1, mww2, mwb2);
    // student base: g_comb[4096,256] @ g_sw1p[256,512] + sb1
    tgemm<0><<<dim3(4, B_ / 128), 256, TG_SMEM>>>(gcomb, 256, gsw1p, 512, 256, sb1,
                                                  nullptr, nullptr, nullptr, gbase, 512);
    student_kernel<<<B_, 128>>>(x, sw1, sw2, sb2, out);
}

// round 10
// speedup vs baseline: 1.0143x; 1.0143x over previous
#include <cuda_runtime.h>
#include <math.h>
#include <stdint.h>

#define B_    4096
#define MROWS (B_ * 128)   // 524288

// ---------------- global scratch ----------------
__device__ float g_h[(size_t)MROWS * 128];
__device__ float g_qkv[(size_t)MROWS * 384];
__device__ float g_attn[(size_t)MROWS * 128];
__device__ float g_ch1[(size_t)MROWS * 64];
__device__ float g_comb[(size_t)B_ * 256];
__device__ float g_mw[(size_t)B_ * 4];
__device__ float g_base[(size_t)B_ * 512];
__device__ float g_sw1p[256 * 512];   // folded student weight [256,512] row-major

typedef unsigned long long u64t;

__device__ __forceinline__ float siluf(float x) { return x / (1.f + __expf(-x)); }
__device__ __forceinline__ float tanh_fast(float x) { return 1.f - 2.f / (__expf(2.f * x) + 1.f); }
__device__ __forceinline__ void fma2(u64t& d, u64t a, u64t b) {
    asm("fma.rn.f32x2 %0, %1, %2, %0;" : "+l"(d) : "l"(a), "l"(b));
}
__device__ __forceinline__ u64t pk2(float x, float y) {
    u64t r; asm("mov.b64 %0, {%1, %2};" : "=l"(r) : "f"(x), "f"(y)); return r;
}
__device__ __forceinline__ float2 up2(u64t v) {
    float2 r; asm("mov.b64 {%0, %1}, %2;" : "=f"(r.x), "=f"(r.y) : "l"(v)); return r;
}
__device__ __forceinline__ uint32_t smem_u32(const void* p) {
    uint32_t a;
    asm("{ .reg .u64 t; cvta.to.shared.u64 t, %1; cvt.u32.u64 %0, t; }" : "=r"(a) : "l"(p));
    return a;
}

// ---- cp.async ----
__device__ __forceinline__ void cp16(uint32_t dst, const void* src) {
    asm volatile("cp.async.ca.shared.global [%0], [%1], 16;" :: "r"(dst), "l"(src));
}
__device__ __forceinline__ void cp_commit() { asm volatile("cp.async.commit_group;" ::: "memory"); }
template <int N>
__device__ __forceinline__ void cp_wait() { asm volatile("cp.async.wait_group %0;" :: "n"(N) : "memory"); }

// ---- tf32 mma.sync m16n8k8 ----
__device__ __forceinline__ void mma8(float* c, const uint32_t* a, uint32_t b0, uint32_t b1) {
    asm volatile(
        "mma.sync.aligned.m16n8k8.row.col.f32.tf32.tf32.f32 "
        "{%0,%1,%2,%3}, {%4,%5,%6,%7}, {%8,%9}, {%0,%1,%2,%3};"
        : "+f"(c[0]), "+f"(c[1]), "+f"(c[2]), "+f"(c[3])
        : "r"(a[0]), "r"(a[1]), "r"(a[2]), "r"(a[3]), "r"(b0), "r"(b1));
}

// split fp32 into tf32 hi + tf32 lo (3xTF32 compensation)
__device__ __forceinline__ void split_tf32(uint32_t raw, uint32_t& hi, uint32_t& lo) {
    float x = __uint_as_float(raw);
    float h, l;
    asm("cvt.rna.tf32.f32 %0, %1;" : "=f"(h) : "f"(x));
    float r = x - h;
    asm("cvt.rna.tf32.f32 %0, %1;" : "=f"(l) : "f"(r));
    hi = __float_as_uint(h);
    lo = __float_as_uint(l);
}

// ---------------- tf32 tensor GEMM (3xTF32, 128 threads, B pre-split in smem) ---------
// C[bm:bm+128, bn:bn+128] = A[128,Ktot] @ W[Ktot, ldb](cols bn..) + epilogue
// MODE: 0 bias, 1 relu, 2 residual+LayerNorm (N==128, grid.x==1, ldc==128), 3 silu
#define ASZ  18432                 // 128 * 36 floats (bytes)
#define BSZ2 33792                 // 32 * 132 u64 (hi,lo interleaved) (bytes)
#define TG_SMEM (2 * ASZ + 2 * BSZ2)   // 104448
template <int MODE>
__global__ void __launch_bounds__(128, 2) tgemm(const float* __restrict__ A, int lda,
                                                const float* __restrict__ W, int ldb, int Ktot,
                                                const float* __restrict__ bias,
                                                const float* __restrict__ res,
                                                const float* __restrict__ gma,
                                                const float* __restrict__ bta,
                                                float* __restrict__ C, int ldc) {
    extern __shared__ char dsm[];
    const uint32_t sbase = smem_u32(dsm);
    const int t = threadIdx.x;
    const int w = t >> 5, lane = t & 31;
    const int g = lane >> 2, t4 = lane & 3;
    const int bn = blockIdx.x * 128, bm = blockIdx.y * 128;
    const int wrow = w * 32;

    float acc0[16][4], acc1[16][4];
#pragma unroll
    for (int j = 0; j < 16; j++)
#pragma unroll
        for (int q = 0; q < 4; q++) { acc0[j][q] = 0.f; acc1[j][q] = 0.f; }

    const int P = Ktot >> 5;
    const int brow = t >> 5;          // B staging rows: brow + 4*i, i<8
    const int bc4 = (t & 31) * 4;

    float4 breg[8];
    // ---- prologue: stage tile 0 ----
    {
#pragma unroll
        for (int i = 0; i < 8; i++) {
            int idx = t + i * 128;
            int row = idx >> 3, c4 = (idx & 7) * 4;
            cp16(sbase + (uint32_t)(row * 36 + c4) * 4u, A + (size_t)(bm + row) * lda + c4);
        }
        cp_commit();
#pragma unroll
        for (int i = 0; i < 8; i++)
            breg[i] = *(const float4*)(W + (size_t)(brow + i * 4) * ldb + bn + bc4);
        uint2* Bs = (uint2*)(dsm + 2 * ASZ);
#pragma unroll
        for (int i = 0; i < 8; i++) {
            uint2 e0, e1, e2, e3;
            split_tf32(__float_as_uint(breg[i].x), e0.x, e0.y);
            split_tf32(__float_as_uint(breg[i].y), e1.x, e1.y);
            split_tf32(__float_as_uint(breg[i].z), e2.x, e2.y);
            split_tf32(__float_as_uint(breg[i].w), e3.x, e3.y);
            uint2* dst = Bs + (brow + i * 4) * 132 + bc4;
            *(uint4*)(dst + 0) = make_uint4(e0.x, e0.y, e1.x, e1.y);
            *(uint4*)(dst + 2) = make_uint4(e2.x, e2.y, e3.x, e3.y);
        }
    }

    for (int p = 0; p < P; p++) {
        cp_wait<0>();
        __syncthreads();
        const bool more = (p + 1 < P);
        if (more) {
            const int buf = (p + 1) & 1;
            const int kof = (p + 1) * 32;
#pragma unroll
            for (int i = 0; i < 8; i++) {
                int idx = t + i * 128;
                int row = idx >> 3, c4 = (idx & 7) * 4;
                cp16(sbase + (uint32_t)(buf * ASZ + (row * 36 + c4) * 4),
                     A + (size_t)(bm + row) * lda + kof + c4);
            }
            cp_commit();
#pragma unroll
            for (int i = 0; i < 8; i++)
                breg[i] = *(const float4*)(W + (size_t)(kof + brow + i * 4) * ldb + bn + bc4);
        }
        // ---- compute from buf p&1 ----
        const uint32_t* Asu = (const uint32_t*)(dsm + (p & 1) * ASZ);
        const uint2* Bsu = (const uint2*)(dsm + 2 * ASZ + (p & 1) * BSZ2);
#pragma unroll
        for (int ks = 0; ks < 4; ks++) {
            const int k0 = ks * 8;
            const int r = wrow + g;
            uint32_t a0h[4], a0l[4], a1h[4], a1l[4];
            split_tf32(Asu[(r) * 36 + k0 + t4],          a0h[0], a0l[0]);
            split_tf32(Asu[(r + 8) * 36 + k0 + t4],      a0h[1], a0l[1]);
            split_tf32(Asu[(r) * 36 + k0 + t4 + 4],      a0h[2], a0l[2]);
            split_tf32(Asu[(r + 8) * 36 + k0 + t4 + 4],  a0h[3], a0l[3]);
            split_tf32(Asu[(r + 16) * 36 + k0 + t4],     a1h[0], a1l[0]);
            split_tf32(Asu[(r + 24) * 36 + k0 + t4],     a1h[1], a1l[1]);
            split_tf32(Asu[(r + 16) * 36 + k0 + t4 + 4], a1h[2], a1l[2]);
            split_tf32(Asu[(r + 24) * 36 + k0 + t4 + 4], a1h[3], a1l[3]);
#pragma unroll
            for (int j = 0; j < 16; j++) {
                uint2 b0 = Bsu[(k0 + t4) * 132 + j * 8 + g];
                uint2 b1 = Bsu[(k0 + t4 + 4) * 132 + j * 8 + g];
                mma8(acc0[j], a0h, b0.x, b1.x);
                mma8(acc0[j], a0l, b0.x, b1.x);
                mma8(acc0[j], a0h, b0.y, b1.y);
                mma8(acc1[j], a1h, b0.x, b1.x);
                mma8(acc1[j], a1l, b0.x, b1.x);
                mma8(acc1[j], a1h, b0.y, b1.y);
            }
        }
        if (more) {
            const int buf = (p + 1) & 1;
            uint2* Bs = (uint2*)(dsm + 2 * ASZ + buf * BSZ2);
#pragma unroll
            for (int i = 0; i < 8; i++) {
                uint2 e0, e1, e2, e3;
                split_tf32(__float_as_uint(breg[i].x), e0.x, e0.y);
                split_tf32(__float_as_uint(breg[i].y), e1.x, e1.y);
                split_tf32(__float_as_uint(breg[i].z), e2.x, e2.y);
                split_tf32(__float_as_uint(breg[i].w), e3.x, e3.y);
                uint2* dst = Bs + (brow + i * 4) * 132 + bc4;
                *(uint4*)(dst + 0) = make_uint4(e0.x, e0.y, e1.x, e1.y);
                *(uint4*)(dst + 2) = make_uint4(e2.x, e2.y, e3.x, e3.y);
            }
        }
    }

    // ---------------- epilogue ----------------
    float2 bias2[16];
#pragma unroll
    for (int j = 0; j < 16; j++) bias2[j] = *(const float2*)(bias + bn + j * 8 + 2 * t4);

    if (MODE == 2) {
#pragma unroll
        for (int i = 0; i < 2; i++) {
            float (*ac)[4] = i ? acc1 : acc0;
#pragma unroll
            for (int h = 0; h < 2; h++) {
                const int row = bm + wrow + i * 16 + h * 8 + g;
                const float* rp = res + (size_t)row * 128 + 2 * t4;
                float sum = 0.f;
#pragma unroll
                for (int j = 0; j < 16; j++) {
                    float2 rv = *(const float2*)(rp + j * 8);
                    float v0 = ac[j][2 * h] + bias2[j].x + rv.x;
                    float v1 = ac[j][2 * h + 1] + bias2[j].y + rv.y;
                    ac[j][2 * h] = v0;
                    ac[j][2 * h + 1] = v1;
                    sum += v0 + v1;
                }
                sum += __shfl_xor_sync(0xffffffffu, sum, 1);
                sum += __shfl_xor_sync(0xffffffffu, sum, 2);
                const float mean = sum * (1.f / 128.f);
                float var = 0.f;
#pragma unroll
                for (int j = 0; j < 16; j++) {
                    float v0 = ac[j][2 * h] - mean;
                    float v1 = ac[j][2 * h + 1] - mean;
                    ac[j][2 * h] = v0;
                    ac[j][2 * h + 1] = v1;
                    var += v0 * v0 + v1 * v1;
                }
                var += __shfl_xor_sync(0xffffffffu, var, 1);
                var += __shfl_xor_sync(0xffffffffu, var, 2);
                const float rs = rsqrtf(var * (1.f / 128.f) + 1e-5f);
                float* cp = C + (size_t)row * 128 + 2 * t4;
#pragma unroll
                for (int j = 0; j < 16; j++) {
                    float2 gv = *(const float2*)(gma + j * 8 + 2 * t4);
                    float2 tv = *(const float2*)(bta + j * 8 + 2 * t4);
                    float2 o;
                    o.x = fmaf(gv.x, ac[j][2 * h] * rs, tv.x);
                    o.y = fmaf(gv.y, ac[j][2 * h + 1] * rs, tv.y);
                    *(float2*)(cp + j * 8) = o;
                }
            }
        }
    } else {
#pragma unroll
        for (int i = 0; i < 2; i++) {
            float (*ac)[4] = i ? acc1 : acc0;
#pragma unroll
            for (int h = 0; h < 2; h++) {
                const int row = bm + wrow + i * 16 + h * 8 + g;
                float* cp = C + (size_t)row * ldc + bn + 2 * t4;
#pragma unroll
                for (int j = 0; j < 16; j++) {
                    float2 o;
                    o.x = ac[j][2 * h] + bias2[j].x;
                    o.y = ac[j][2 * h + 1] + bias2[j].y;
                    if (MODE == 1) { o.x = fmaxf(o.x, 0.f); o.y = fmaxf(o.y, 0.f); }
                    if (MODE == 3) { o.x = siluf(o.x); o.y = siluf(o.y); }
                    *(float2*)(cp + j * 8) = o;
                }
            }
        }
    }
}

// ---------------- time embedding ----------------
__global__ void __launch_bounds__(256) time_kernel(const int* __restrict__ ts,
                                                   const float* __restrict__ w1,
                                                   const float* __restrict__ b1,
                                                   const float* __restrict__ w2,
                                                   const float* __restrict__ b2) {
    __shared__ float te[128];
    __shared__ float hid[256];
    const int b = blockIdx.x, t = threadIdx.x;
    const float tf = (float)ts[b];
    if (t < 128) {
        int i = t & 63;
        float freq = expf(-0.14391156831212787f * (float)i);
        float arg = tf * freq;
        te[t] = (t < 64) ? cosf(arg) : sinf(arg);
    }
    __syncthreads();
    float a = b1[t];
    for (int i = 0; i < 128; i++) a = fmaf(te[i], w1[i * 256 + t], a);
    hid[t] = siluf(a);
    __syncthreads();
    if (t < 128) {
        float a2 = b2[t];
        for (int i = 0; i < 256; i++) a2 = fmaf(hid[i], w2[i * 128 + t], a2);
        g_comb[(size_t)b * 256 + t] = a2;
    }
}

// ---------------- cond layer1 ----------------
__global__ void __launch_bounds__(256) condh1_kernel(const float* __restrict__ cond,
                                                     const float* __restrict__ w1,
                                                     const float* __restrict__ b1) {
    const size_t row = (size_t)blockIdx.x * 32 + (threadIdx.x >> 3);
    const int dg = threadIdx.x & 7;
    const float* cp = cond + row * 6;
    float c0 = cp[0], c1 = cp[1], c2 = cp[2], c3 = cp[3], c4 = cp[4], c5 = cp[5];
    float o[8];
#pragma unroll
    for (int j = 0; j < 8; j++) {
        int dd = dg * 8 + j;
        float a = b1[dd];
        a = fmaf(c0, w1[0 * 64 + dd], a);
        a = fmaf(c1, w1[1 * 64 + dd], a);
        a = fmaf(c2, w1[2 * 64 + dd], a);
        a = fmaf(c3, w1[3 * 64 + dd], a);
        a = fmaf(c4, w1[4 * 64 + dd], a);
        a = fmaf(c5, w1[5 * 64 + dd], a);
        o[j] = siluf(a);
    }
    float4 v0, v1;
    v0.x = o[0]; v0.y = o[1]; v0.z = o[2]; v0.w = o[3];
    v1.x = o[4]; v1.y = o[5]; v1.z = o[6]; v1.w = o[7];
    *(float4*)(g_ch1 + row * 64 + dg * 8) = v0;
    *(float4*)(g_ch1 + row * 64 + dg * 8 + 4) = v1;
}

// ---------------- attention (fp32, f32x2) ----------------
#define ATTN_SMEM ((8192 + 128 * 129) * 4)
__global__ void __launch_bounds__(128) attn_kernel() {
    extern __shared__ float smem[];
    float (*ks)[32] = (float(*)[32])smem;
    float (*vs)[32] = (float(*)[32])(smem + 4096);
    float (*sc)[129] = (float(*)[129])(smem + 8192);
    const int b = blockIdx.x >> 2;
    const int hd = blockIdx.x & 3;
    const int t = threadIdx.x;
    const float* rowp = g_qkv + ((size_t)b * 128 + t) * 384;
#pragma unroll
    for (int c = 0; c < 8; c++)
        *(float4*)&ks[t][c * 4] = *(const float4*)(rowp + 128 + hd * 32 + c * 4);
#pragma unroll
    for (int c = 0; c < 8; c++)
        *(float4*)&vs[t][c * 4] = *(const float4*)(rowp + 256 + hd * 32 + c * 4);
    u64t q2[16];
#pragma unroll
    for (int c = 0; c < 8; c++) {
        ulonglong2 qv = *(const ulonglong2*)(rowp + hd * 32 + c * 4);
        q2[2 * c] = qv.x;
        q2[2 * c + 1] = qv.y;
    }
    __syncthreads();
    const float scale = 0.17677669529663687f;
    float m = -1e30f;
    for (int j = 0; j < 128; j++) {
        u64t d2 = 0ULL;
        const ulonglong2* kp = (const ulonglong2*)&ks[j][0];
#pragma unroll
        for (int c = 0; c < 8; c++) {
            ulonglong2 kv = kp[c];
            fma2(d2, q2[2 * c], kv.x);
            fma2(d2, q2[2 * c + 1], kv.y);
        }
        float2 dp = up2(d2);
        float s = (dp.x + dp.y) * scale;
        sc[t][j] = s;
        m = fmaxf(m, s);
    }
    float l = 0.f;
    u64t acc2[16];
#pragma unroll
    for (int i = 0; i < 16; i++) acc2[i] = 0ULL;
    for (int j = 0; j < 128; j++) {
        float e = __expf(sc[t][j] - m);
        l += e;
        u64t e2 = pk2(e, e);
        const ulonglong2* vp = (const ulonglong2*)&vs[j][0];
#pragma unroll
        for (int c = 0; c < 8; c++) {
            ulonglong2 vv = vp[c];
            fma2(acc2[2 * c], e2, vv.x);
            fma2(acc2[2 * c + 1], e2, vv.y);
        }
    }
    const float inv = 1.f / l;
    float* op = g_attn + ((size_t)b * 128 + t) * 128 + hd * 32;
#pragma unroll
    for (int c = 0; c < 16; c++) {
        float2 p = up2(acc2[c]);
        p.x *= inv;
        p.y *= inv;
        *(float2*)(op + 2 * c) = p;
    }
}

// ---------------- mean pool ----------------
__global__ void __launch_bounds__(128) pool_kernel() {
    const int b = blockIdx.x, d = threadIdx.x;
    const float* p = g_h + (size_t)b * 128 * 128 + d;
    float s = 0.f;
    for (int j = 0; j < 128; j++) s += p[j * 128];
    g_comb[(size_t)b * 256 + 128 + d] = s * (1.f / 128.f);
}

// ---------------- mixture weights ----------------
__global__ void __launch_bounds__(128) mw_kernel(const float* __restrict__ w1,
                                                 const float* __restrict__ b1,
                                                 const float* __restrict__ w2,
                                                 const float* __restrict__ b2) {
    __shared__ float scm[256];
    __shared__ float hid[128];
    __shared__ float lg[4];
    const int b = blockIdx.x, t = threadIdx.x;
    scm[t] = g_comb[(size_t)b * 256 + t];
    scm[128 + t] = g_comb[(size_t)b * 256 + 128 + t];
    __syncthreads();
    float a = b1[t];
    for (int i = 0; i < 256; i++) a = fmaf(scm[i], w1[i * 128 + t], a);
    hid[t] = siluf(a);
    __syncthreads();
    if (t < 4) {
        float a2 = b2[t];
        for (int j = 0; j < 128; j++) a2 = fmaf(hid[j], w2[j * 4 + t], a2);
        lg[t] = a2;
    }
    __syncthreads();
    if (t == 0) {
        float mm = fmaxf(fmaxf(lg[0], lg[1]), fmaxf(lg[2], lg[3]));
        float e0 = __expf(lg[0] - mm), e1 = __expf(lg[1] - mm);
        float e2 = __expf(lg[2] - mm), e3 = __expf(lg[3] - mm);
        float inv = 1.f / (e0 + e1 + e2 + e3);
        g_mw[(size_t)b * 4 + 0] = e0 * inv;
        g_mw[(size_t)b * 4 + 1] = e1 * inv;
        g_mw[(size_t)b * 4 + 2] = e2 * inv;
        g_mw[(size_t)b * 4 + 3] = e3 * inv;
    }
}

// ---------------- student fold pack (plain row-major [256,512]) ----------------
__global__ void __launch_bounds__(256) packsw1(const float* __restrict__ sw1) {
    int idx = blockIdx.x * 256 + threadIdx.x;  // < 256*512
    int i = idx >> 9;
    int n = idx & 511;
    g_sw1p[idx] = sw1[((size_t)(n >> 7) * 258 + 2 + i) * 128 + (n & 127)];
}

// ---------------- students ----------------
__global__ void __launch_bounds__(128) student_kernel(const float* __restrict__ x,
                                                      const float* __restrict__ sw1,
                                                      const float* __restrict__ sw2,
                                                      const float* __restrict__ sb2,
                                                      float* __restrict__ out) {
    __shared__ float sb[512], w0[512], w1s[512], s2a[512], s2b[512];
    __shared__ float smw[4], sbias2[8];
    const int b = blockIdx.x, t = threadIdx.x;
    for (int i = t; i < 512; i += 128) {
        sb[i] = g_base[(size_t)b * 512 + i];
        int k = i >> 7, j = i & 127;
        w0[i] = sw1[((size_t)k * 258 + 0) * 128 + j];
        w1s[i] = sw1[((size_t)k * 258 + 1) * 128 + j];
        s2a[i] = sw2[i * 2 + 0];
        s2b[i] = sw2[i * 2 + 1];
    }
    if (t < 4) smw[t] = g_mw[(size_t)b * 4 + t];
    if (t < 8) sbias2[t] = sb2[t];
    __syncthreads();
    const float x0 = x[(size_t)b * 256 + t];
    const float x1 = x[(size_t)b * 256 + 128 + t];
    float o0 = 0.f, o1 = 0.f;
#pragma unroll
    for (int k = 0; k < 4; k++) {
        float a0 = 0.f, a1 = 0.f;
        for (int j = 0; j < 128; j++) {
            int idx = k * 128 + j;
            float hv = tanh_fast(fmaf(x1, w1s[idx], fmaf(x0, w0[idx], sb[idx])));
            a0 = fmaf(hv, s2a[idx], a0);
            a1 = fmaf(hv, s2b[idx], a1);
        }
        float wk = smw[k];
        o0 = fmaf(wk, a0 + sbias2[k * 2 + 0], o0);
        o1 = fmaf(wk, a1 + sbias2[k * 2 + 1], o1);
    }
    out[(size_t)b * 256 + t] = o0;
    out[(size_t)b * 256 + 128 + t] = o1;
}

// ---------------- launcher ----------------
extern "C" void kernel_launch(void* const* d_in, const int* in_sizes, int n_in,
                              void* d_out, int out_size) {
    const float* x    = (const float*)d_in[0];
    const int*   ts   = (const int*)d_in[1];
    const float* cond = (const float*)d_in[2];
    const float* t_w1 = (const float*)d_in[3];
    const float* t_b1 = (const float*)d_in[4];
    const float* t_w2 = (const float*)d_in[5];
    const float* t_b2 = (const float*)d_in[6];
    const float* c_w1 = (const float*)d_in[7];
    const float* c_b1 = (const float*)d_in[8];
    const float* c_w2 = (const float*)d_in[9];
    const float* c_b2 = (const float*)d_in[10];
    const float* wqkv = (const float*)d_in[11];
    const float* bqkv = (const float*)d_in[12];
    const float* wo   = (const float*)d_in[13];
    const float* bo   = (const float*)d_in[14];
    const float* ln1g = (const float*)d_in[15];
    const float* ln1b = (const float*)d_in[16];
    const float* ffw1 = (const float*)d_in[17];
    const float* ffb1 = (const float*)d_in[18];
    const float* ffw2 = (const float*)d_in[19];
    const float* ffb2 = (const float*)d_in[20];
    const float* ln2g = (const float*)d_in[21];
    const float* ln2b = (const float*)d_in[22];
    const float* mww1 = (const float*)d_in[23];
    const float* mwb1 = (const float*)d_in[24];
    const float* mww2 = (const float*)d_in[25];
    const float* mwb2 = (const float*)d_in[26];
    const float* sw1  = (const float*)d_in[27];
    const float* sb1  = (const float*)d_in[28];
    const float* sw2  = (const float*)d_in[29];
    const float* sb2  = (const float*)d_in[30];
    float* out = (float*)d_out;

    float *gh, *gqkv, *gattn, *gch1, *gcomb, *gbase, *gsw1p;
    cudaGetSymbolAddress((void**)&gh, g_h);
    cudaGetSymbolAddress((void**)&gqkv, g_qkv);
    cudaGetSymbolAddress((void**)&gattn, g_attn);
    cudaGetSymbolAddress((void**)&gch1, g_ch1);
    cudaGetSymbolAddress((void**)&gcomb, g_comb);
    cudaGetSymbolAddress((void**)&gbase, g_base);
    cudaGetSymbolAddress((void**)&gsw1p, g_sw1p);

    cudaFuncSetAttribute(attn_kernel, cudaFuncAttributeMaxDynamicSharedMemorySize, ATTN_SMEM);
    cudaFuncSetAttribute(tgemm<0>, cudaFuncAttributeMaxDynamicSharedMemorySize, TG_SMEM);
    cudaFuncSetAttribute(tgemm<1>, cudaFuncAttributeMaxDynamicSharedMemorySize, TG_SMEM);
    cudaFuncSetAttribute(tgemm<2>, cudaFuncAttributeMaxDynamicSharedMemorySize, TG_SMEM);
    cudaFuncSetAttribute(tgemm<3>, cudaFuncAttributeMaxDynamicSharedMemorySize, TG_SMEM);

    time_kernel<<<B_, 256>>>(ts, t_w1, t_b1, t_w2, t_b2);
    condh1_kernel<<<MROWS / 32, 256>>>(cond, c_w1, c_b1);
    packsw1<<<(256 * 512) / 256, 256>>>(sw1);
    // cond layer2: silu(g_ch1 @ c_w2 + b)  [M,64]@[64,128]
    tgemm<3><<<dim3(1, MROWS / 128), 128, TG_SMEM>>>(gch1, 64, c_w2, 128, 64, c_b2,
                                                     nullptr, nullptr, nullptr, gh, 128);
    for (int l = 0; l < 2; l++) {
        // qkv
        tgemm<0><<<dim3(3, MROWS / 128), 128, TG_SMEM>>>(gh, 128, wqkv + (size_t)l * 49152, 384,
                                                         128, bqkv + l * 384, nullptr, nullptr,
                                                         nullptr, gqkv, 384);
        attn_kernel<<<B_ * 4, 128, ATTN_SMEM>>>();
        // o-proj + res + LN
        tgemm<2><<<dim3(1, MROWS / 128), 128, TG_SMEM>>>(gattn, 128, wo + (size_t)l * 16384, 128,
                                                         128, bo + l * 128, gh, ln1g + l * 128,
                                                         ln1b + l * 128, gh, 128);
        // ffn1 relu
        tgemm<1><<<dim3(2, MROWS / 128), 128, TG_SMEM>>>(gh, 128, ffw1 + (size_t)l * 32768, 256,
                                                         128, ffb1 + l * 256, nullptr, nullptr,
                                                         nullptr, gqkv, 256);
        // ffn2 + res + LN
        tgemm<2><<<dim3(1, MROWS / 128), 128, TG_SMEM>>>(gqkv, 256, ffw2 + (size_t)l * 32768, 128,
                                                         256, ffb2 + l * 128, gh, ln2g + l * 128,
                                                         ln2b + l * 128, gh, 128);
    }
    pool_kernel<<<B_, 128>>>();
    mw_kernel<<<B_, 128>>>(mww1, mwb1, mww2, mwb2);
    // student base: g_comb[4096,256] @ g_sw1p[256,512] + sb1
    tgemm<0><<<dim3(4, B_ / 128), 128, TG_SMEM>>>(gcomb, 256, gsw1p, 512, 256, sb1,
                                                  nullptr, nullptr, nullptr, gbase, 512);
    student_kernel<<<B_, 128>>>(x, sw1, sw2, sb2, out);
}

// round 12
// speedup vs baseline: 1.2208x; 1.2036x over previous
#include <cuda_runtime.h>
#include <math.h>
#include <stdint.h>

#define B_    4096
#define MROWS (B_ * 128)   // 524288

// ---------------- global scratch (aliased to keep module-load footprint small) --------
__device__ float g_h[(size_t)MROWS * 128];      // fp32 activations (residual path)
__device__ float g_qkv[(size_t)MROWS * 384];    // qkv fp32; ALIASED as ffn_pack (uint2, 512MB<768MB)
__device__ float g_comb[(size_t)B_ * 256];
__device__ float g_mw[(size_t)B_ * 4];
__device__ float g_base[(size_t)B_ * 512];
__device__ uint2 g_h_pack[(size_t)MROWS * 64];     // packed bf16 hi/lo activations
__device__ uint2 g_attn_pack[(size_t)MROWS * 64];  // ALIASED as ch1_pack (128MB<256MB)
__device__ uint2 g_comb_pack[(size_t)B_ * 128];
__device__ uint2 g_wp[200704];                  // packed weights

// packed weight offsets (uint2 units)
#define OFF_QKV0 0
#define OFF_QKV1 24576
#define OFF_WO0  49152
#define OFF_WO1  57344
#define OFF_FF10 65536
#define OFF_FF11 81920
#define OFF_FF20 98304
#define OFF_FF21 114688
#define OFF_CW2  131072
#define OFF_SW1  135168

typedef unsigned long long u64t;

__device__ __forceinline__ float siluf(float x) { return x / (1.f + __expf(-x)); }
__device__ __forceinline__ float tanh_fast(float x) { return 1.f - 2.f / (__expf(2.f * x) + 1.f); }
__device__ __forceinline__ void fma2(u64t& d, u64t a, u64t b) {
    asm("fma.rn.f32x2 %0, %1, %2, %0;" : "+l"(d) : "l"(a), "l"(b));
}
__device__ __forceinline__ u64t pk2(float x, float y) {
    u64t r; asm("mov.b64 %0, {%1, %2};" : "=l"(r) : "f"(x), "f"(y)); return r;
}
__device__ __forceinline__ float2 up2(u64t v) {
    float2 r; asm("mov.b64 {%0, %1}, %2;" : "=f"(r.x), "=f"(r.y) : "l"(v)); return r;
}
__device__ __forceinline__ uint32_t smem_u32(const void* p) {
    uint32_t a;
    asm("{ .reg .u64 t; cvta.to.shared.u64 t, %1; cvt.u32.u64 %0, t; }" : "=r"(a) : "l"(p));
    return a;
}

// pack two fp32 (v0 = even k, v1 = odd k) into {hi bf16x2, lo bf16x2}
__device__ __forceinline__ uint2 pack_bf16_pair(float v0, float v1) {
    uint32_t hi;
    asm("cvt.rn.bf16x2.f32 %0, %1, %2;" : "=r"(hi) : "f"(v1), "f"(v0));  // upper=v1, lower=v0
    float b0 = __uint_as_float(hi << 16);
    float b1 = __uint_as_float(hi & 0xffff0000u);
    uint32_t lo;
    asm("cvt.rn.bf16x2.f32 %0, %1, %2;" : "=r"(lo) : "f"(v1 - b1), "f"(v0 - b0));
    return make_uint2(hi, lo);
}

// ---- cp.async ----
__device__ __forceinline__ void cp16(uint32_t dst, const void* src) {
    asm volatile("cp.async.ca.shared.global [%0], [%1], 16;" :: "r"(dst), "l"(src));
}
__device__ __forceinline__ void cp_commit() { asm volatile("cp.async.commit_group;" ::: "memory"); }
template <int N>
__device__ __forceinline__ void cp_wait() { asm volatile("cp.async.wait_group %0;" :: "n"(N) : "memory"); }

// ---- bf16 mma.sync m16n8k16 ----
__device__ __forceinline__ void mma16(float* c, const uint32_t* a, uint32_t b0, uint32_t b1) {
    asm volatile(
        "mma.sync.aligned.m16n8k16.row.col.f32.bf16.bf16.f32 "
        "{%0,%1,%2,%3}, {%4,%5,%6,%7}, {%8,%9}, {%0,%1,%2,%3};"
        : "+f"(c[0]), "+f"(c[1]), "+f"(c[2]), "+f"(c[3])
        : "r"(a[0]), "r"(a[1]), "r"(a[2]), "r"(a[3]), "r"(b0), "r"(b1));
}

// ---------------- weight pre-pack: W[K][N] -> per-128-col-chunk [nn][kp] uint2 ----------
__global__ void __launch_bounds__(256) packw(const float* __restrict__ W, uint2* __restrict__ dst,
                                             int K, int N) {
    int kp2 = K >> 1;
    int idx = blockIdx.x * 256 + threadIdx.x;
    if (idx >= N * kp2) return;
    int n = idx / kp2, kp = idx - n * kp2;
    int chunk = n >> 7, nn = n & 127;
    dst[((size_t)chunk * 128 + nn) * kp2 + kp] =
        pack_bf16_pair(W[(size_t)(2 * kp) * N + n], W[(size_t)(2 * kp + 1) * N + n]);
}
// folded student weight: logical W[i=0..255][n=0..511] = sw1[n>>7][2+i][n&127]
__global__ void __launch_bounds__(256) packsw1(const float* __restrict__ sw1, uint2* __restrict__ dst) {
    int idx = blockIdx.x * 256 + threadIdx.x;   // < 512*128
    if (idx >= 512 * 128) return;
    int n = idx / 128, kp = idx - (idx / 128) * 128;
    int chunk = n >> 7, nn = n & 127;
    float v0 = sw1[((size_t)(n >> 7) * 258 + 2 + 2 * kp) * 128 + nn];
    float v1 = sw1[((size_t)(n >> 7) * 258 + 2 + 2 * kp + 1) * 128 + nn];
    dst[((size_t)chunk * 128 + nn) * 128 + kp] = pack_bf16_pair(v0, v1);
}

// ---------------- bf16 2-term tensor GEMM ----------------
// C[bm:bm+128, bn:bn+128] = A[128,Ktot] @ W[Ktot,...] + epilogue
// A, B pre-packed. MODE: 0 bias fp32-out, 1 relu pack-out, 2 res+LN both-out, 3 silu both-out
#define RS 20                        // smem row stride in uint2
#define TBUF 20480                   // 128 * 20 * 8 bytes
#define TG_SMEM (4 * TBUF)           // 81920
template <int MODE>
__global__ void __launch_bounds__(128, 2) tgemm(const uint2* __restrict__ Apack,
                                                const uint2* __restrict__ Bpack,
                                                int Ktot,
                                                const float* __restrict__ bias,
                                                const float* __restrict__ res,
                                                const float* __restrict__ gma,
                                                const float* __restrict__ bta,
                                                float* __restrict__ C, int ldc,
                                                uint2* __restrict__ Cpack, int ldcp) {
    extern __shared__ char dsm[];
    const uint32_t sbase = smem_u32(dsm);
    const int t = threadIdx.x;
    const int w = t >> 5, lane = t & 31;
    const int g = lane >> 2, t4 = lane & 3;
    const int bn = blockIdx.x * 128, bm = blockIdx.y * 128;
    const int wrow = w * 32;
    const int kpTot = Ktot >> 1;

    float acc0[16][4], acc1[16][4];
#pragma unroll
    for (int j = 0; j < 16; j++)
#pragma unroll
        for (int q = 0; q < 4; q++) { acc0[j][q] = 0.f; acc1[j][q] = 0.f; }

    const int P = Ktot >> 5;
    const uint2* Bbase = Bpack + (size_t)blockIdx.x * 128 * kpTot;
    const int srow = t >> 3;        // staging row (8 lanes per row)
    const int sj = t & 7;           // 16B chunk within the 128B row slice

    // ---- prologue: stage tile 0 ----
#pragma unroll
    for (int i = 0; i < 8; i++) {
        int row = srow + i * 16;
        cp16(sbase + (uint32_t)(row * RS * 8 + sj * 16),
             Apack + (size_t)(bm + row) * kpTot + sj * 2);
        cp16(sbase + (uint32_t)(2 * TBUF + row * RS * 8 + sj * 16),
             Bbase + (size_t)row * kpTot + sj * 2);
    }
    cp_commit();

    for (int p = 0; p < P; p++) {
        const bool more = (p + 1 < P);
        if (more) {
            const int buf = (p + 1) & 1;
            const int kpo = (p + 1) * 16;
#pragma unroll
            for (int i = 0; i < 8; i++) {
                int row = srow + i * 16;
                cp16(sbase + (uint32_t)(buf * TBUF + row * RS * 8 + sj * 16),
                     Apack + (size_t)(bm + row) * kpTot + kpo + sj * 2);
                cp16(sbase + (uint32_t)(2 * TBUF + buf * TBUF + row * RS * 8 + sj * 16),
                     Bbase + (size_t)row * kpTot + kpo + sj * 2);
            }
            cp_commit();
            cp_wait<1>();
        } else {
            cp_wait<0>();
        }
        __syncthreads();

        const uint2* As = (const uint2*)(dsm + (p & 1) * TBUF);
        const uint2* Bs = (const uint2*)(dsm + 2 * TBUF + (p & 1) * TBUF);
#pragma unroll
        for (int h2 = 0; h2 < 2; h2++) {
            const int kb = h2 * 8;
            const int r = wrow + g;
            uint32_t a0h[4], a0l[4], a1h[4], a1l[4];
            uint2 q;
            q = As[(r) * RS + kb + t4];          a0h[0] = q.x; a0l[0] = q.y;
            q = As[(r + 8) * RS + kb + t4];      a0h[1] = q.x; a0l[1] = q.y;
            q = As[(r) * RS + kb + t4 + 4];      a0h[2] = q.x; a0l[2] = q.y;
            q = As[(r + 8) * RS + kb + t4 + 4];  a0h[3] = q.x; a0l[3] = q.y;
            q = As[(r + 16) * RS + kb + t4];     a1h[0] = q.x; a1l[0] = q.y;
            q = As[(r + 24) * RS + kb + t4];     a1h[1] = q.x; a1l[1] = q.y;
            q = As[(r + 16) * RS + kb + t4 + 4]; a1h[2] = q.x; a1l[2] = q.y;
            q = As[(r + 24) * RS + kb + t4 + 4]; a1h[3] = q.x; a1l[3] = q.y;
#pragma unroll
            for (int j = 0; j < 16; j++) {
                uint2 b0 = Bs[(j * 8 + g) * RS + kb + t4];
                uint2 b1 = Bs[(j * 8 + g) * RS + kb + t4 + 4];
                mma16(acc0[j], a0h, b0.x, b1.x);
                mma16(acc0[j], a0l, b0.x, b1.x);
                mma16(acc0[j], a0h, b0.y, b1.y);
                mma16(acc1[j], a1h, b0.x, b1.x);
                mma16(acc1[j], a1l, b0.x, b1.x);
                mma16(acc1[j], a1h, b0.y, b1.y);
            }
        }
        __syncthreads();   // protect buffer being staged next iteration
    }

    // ---------------- epilogue ----------------
    float2 bias2[16];
#pragma unroll
    for (int j = 0; j < 16; j++) bias2[j] = *(const float2*)(bias + bn + j * 8 + 2 * t4);

    if (MODE == 2) {
#pragma unroll
        for (int i = 0; i < 2; i++) {
            float (*ac)[4] = i ? acc1 : acc0;
#pragma unroll
            for (int h = 0; h < 2; h++) {
                const int row = bm + wrow + i * 16 + h * 8 + g;
                const float* rp = res + (size_t)row * 128 + 2 * t4;
                float sum = 0.f;
#pragma unroll
                for (int j = 0; j < 16; j++) {
                    float2 rv = *(const float2*)(rp + j * 8);
                    float v0 = ac[j][2 * h] + bias2[j].x + rv.x;
                    float v1 = ac[j][2 * h + 1] + bias2[j].y + rv.y;
                    ac[j][2 * h] = v0;
                    ac[j][2 * h + 1] = v1;
                    sum += v0 + v1;
                }
                sum += __shfl_xor_sync(0xffffffffu, sum, 1);
                sum += __shfl_xor_sync(0xffffffffu, sum, 2);
                const float mean = sum * (1.f / 128.f);
                float var = 0.f;
#pragma unroll
                for (int j = 0; j < 16; j++) {
                    float v0 = ac[j][2 * h] - mean;
                    float v1 = ac[j][2 * h + 1] - mean;
                    ac[j][2 * h] = v0;
                    ac[j][2 * h + 1] = v1;
                    var += v0 * v0 + v1 * v1;
                }
                var += __shfl_xor_sync(0xffffffffu, var, 1);
                var += __shfl_xor_sync(0xffffffffu, var, 2);
                const float rs = rsqrtf(var * (1.f / 128.f) + 1e-5f);
                float* cp = C + (size_t)row * 128 + 2 * t4;
                uint2* pp = Cpack + (size_t)row * ldcp + t4;
#pragma unroll
                for (int j = 0; j < 16; j++) {
                    float2 gv = *(const float2*)(gma + j * 8 + 2 * t4);
                    float2 tv = *(const float2*)(bta + j * 8 + 2 * t4);
                    float2 o;
                    o.x = fmaf(gv.x, ac[j][2 * h] * rs, tv.x);
                    o.y = fmaf(gv.y, ac[j][2 * h + 1] * rs, tv.y);
                    *(float2*)(cp + j * 8) = o;
                    pp[4 * j] = pack_bf16_pair(o.x, o.y);
                }
            }
        }
    } else {
#pragma unroll
        for (int i = 0; i < 2; i++) {
            float (*ac)[4] = i ? acc1 : acc0;
#pragma unroll
            for (int h = 0; h < 2; h++) {
                const int row = bm + wrow + i * 16 + h * 8 + g;
                float* cp = C + (size_t)row * ldc + bn + 2 * t4;
                uint2* pp = Cpack + (size_t)row * ldcp + (bn >> 1) + t4;
#pragma unroll
                for (int j = 0; j < 16; j++) {
                    float2 o;
                    o.x = ac[j][2 * h] + bias2[j].x;
                    o.y = ac[j][2 * h + 1] + bias2[j].y;
                    if (MODE == 1) { o.x = fmaxf(o.x, 0.f); o.y = fmaxf(o.y, 0.f); }
                    if (MODE == 3) { o.x = siluf(o.x); o.y = siluf(o.y); }
                    if (MODE != 1) *(float2*)(cp + j * 8) = o;
                    if (MODE == 1 || MODE == 3) pp[4 * j] = pack_bf16_pair(o.x, o.y);
                }
            }
        }
    }
}

// ---------------- time embedding ----------------
__global__ void __launch_bounds__(256) time_kernel(const int* __restrict__ ts,
                                                   const float* __restrict__ w1,
                                                   const float* __restrict__ b1,
                                                   const float* __restrict__ w2,
                                                   const float* __restrict__ b2) {
    __shared__ float te[128];
    __shared__ float hid[256];
    __shared__ float tout[128];
    const int b = blockIdx.x, t = threadIdx.x;
    const float tf = (float)ts[b];
    if (t < 128) {
        int i = t & 63;
        float freq = expf(-0.14391156831212787f * (float)i);
        float arg = tf * freq;
        te[t] = (t < 64) ? cosf(arg) : sinf(arg);
    }
    __syncthreads();
    float a = b1[t];
    for (int i = 0; i < 128; i++) a = fmaf(te[i], w1[i * 256 + t], a);
    hid[t] = siluf(a);
    __syncthreads();
    if (t < 128) {
        float a2 = b2[t];
        for (int i = 0; i < 256; i++) a2 = fmaf(hid[i], w2[i * 128 + t], a2);
        g_comb[(size_t)b * 256 + t] = a2;
        tout[t] = a2;
    }
    __syncthreads();
    if (t < 64) g_comb_pack[(size_t)b * 128 + t] = pack_bf16_pair(tout[2 * t], tout[2 * t + 1]);
}

// ---------------- cond layer1 -> packed (into ch1_pack alias region) ----------------
__global__ void __launch_bounds__(256) condh1_kernel(const float* __restrict__ cond,
                                                     const float* __restrict__ w1,
                                                     const float* __restrict__ b1,
                                                     uint2* __restrict__ outp) {
    const size_t row = (size_t)blockIdx.x * 32 + (threadIdx.x >> 3);
    const int dg = threadIdx.x & 7;
    const float* cp = cond + row * 6;
    float c0 = cp[0], c1 = cp[1], c2 = cp[2], c3 = cp[3], c4 = cp[4], c5 = cp[5];
    float o[8];
#pragma unroll
    for (int j = 0; j < 8; j++) {
        int dd = dg * 8 + j;
        float a = b1[dd];
        a = fmaf(c0, w1[0 * 64 + dd], a);
        a = fmaf(c1, w1[1 * 64 + dd], a);
        a = fmaf(c2, w1[2 * 64 + dd], a);
        a = fmaf(c3, w1[3 * 64 + dd], a);
        a = fmaf(c4, w1[4 * 64 + dd], a);
        a = fmaf(c5, w1[5 * 64 + dd], a);
        o[j] = siluf(a);
    }
#pragma unroll
    for (int i = 0; i < 4; i++)
        outp[row * 32 + dg * 4 + i] = pack_bf16_pair(o[2 * i], o[2 * i + 1]);
}

// ---------------- attention (fp32 f32x2) -> packed output ----------------
#define ATTN_SMEM ((8192 + 128 * 129) * 4)
__global__ void __launch_bounds__(128) attn_kernel() {
    extern __shared__ float smem[];
    float (*ks)[32] = (float(*)[32])smem;
    float (*vs)[32] = (float(*)[32])(smem + 4096);
    float (*sc)[129] = (float(*)[129])(smem + 8192);
    const int b = blockIdx.x >> 2;
    const int hd = blockIdx.x & 3;
    const int t = threadIdx.x;
    const float* rowp = g_qkv + ((size_t)b * 128 + t) * 384;
#pragma unroll
    for (int c = 0; c < 8; c++)
        *(float4*)&ks[t][c * 4] = *(const float4*)(rowp + 128 + hd * 32 + c * 4);
#pragma unroll
    for (int c = 0; c < 8; c++)
        *(float4*)&vs[t][c * 4] = *(const float4*)(rowp + 256 + hd * 32 + c * 4);
    u64t q2[16];
#pragma unroll
    for (int c = 0; c < 8; c++) {
        ulonglong2 qv = *(const ulonglong2*)(rowp + hd * 32 + c * 4);
        q2[2 * c] = qv.x;
        q2[2 * c + 1] = qv.y;
    }
    __syncthreads();
    const float scale = 0.17677669529663687f;
    float m = -1e30f;
    for (int j = 0; j < 128; j++) {
        u64t d2 = 0ULL;
        const ulonglong2* kp = (const ulonglong2*)&ks[j][0];
#pragma unroll
        for (int c = 0; c < 8; c++) {
            ulonglong2 kv = kp[c];
            fma2(d2, q2[2 * c], kv.x);
            fma2(d2, q2[2 * c + 1], kv.y);
        }
        float2 dp = up2(d2);
        float s = (dp.x + dp.y) * scale;
        sc[t][j] = s;
        m = fmaxf(m, s);
    }
    float l = 0.f;
    u64t acc2[16];
#pragma unroll
    for (int i = 0; i < 16; i++) acc2[i] = 0ULL;
    for (int j = 0; j < 128; j++) {
        float e = __expf(sc[t][j] - m);
        l += e;
        u64t e2 = pk2(e, e);
        const ulonglong2* vp = (const ulonglong2*)&vs[j][0];
#pragma unroll
        for (int c = 0; c < 8; c++) {
            ulonglong2 vv = vp[c];
            fma2(acc2[2 * c], e2, vv.x);
            fma2(acc2[2 * c + 1], e2, vv.y);
        }
    }
    const float inv = 1.f / l;
    uint2* op = g_attn_pack + ((size_t)b * 128 + t) * 64 + hd * 16;
#pragma unroll
    for (int c = 0; c < 16; c++) {
        float2 p = up2(acc2[c]);
        op[c] = pack_bf16_pair(p.x * inv, p.y * inv);
    }
}

// ---------------- mean pool -> fp32 + packed ----------------
__global__ void __launch_bounds__(128) pool_kernel() {
    __shared__ float buf[128];
    const int b = blockIdx.x, d = threadIdx.x;
    const float* p = g_h + (size_t)b * 128 * 128 + d;
    float s = 0.f;
    for (int j = 0; j < 128; j++) s += p[j * 128];
    s *= (1.f / 128.f);
    g_comb[(size_t)b * 256 + 128 + d] = s;
    buf[d] = s;
    __syncthreads();
    if (d < 64) g_comb_pack[(size_t)b * 128 + 64 + d] = pack_bf16_pair(buf[2 * d], buf[2 * d + 1]);
}

// ---------------- mixture weights ----------------
__global__ void __launch_bounds__(128) mw_kernel(const float* __restrict__ w1,
                                                 const float* __restrict__ b1,
                                                 const float* __restrict__ w2,
                                                 const float* __restrict__ b2) {
    __shared__ float scm[256];
    __shared__ float hid[128];
    __shared__ float lg[4];
    const int b = blockIdx.x, t = threadIdx.x;
    scm[t] = g_comb[(size_t)b * 256 + t];
    scm[128 + t] = g_comb[(size_t)b * 256 + 128 + t];
    __syncthreads();
    float a = b1[t];
    for (int i = 0; i < 256; i++) a = fmaf(scm[i], w1[i * 128 + t], a);
    hid[t] = siluf(a);
    __syncthreads();
    if (t < 4) {
        float a2 = b2[t];
        for (int j = 0; j < 128; j++) a2 = fmaf(hid[j], w2[j * 4 + t], a2);
        lg[t] = a2;
    }
    __syncthreads();
    if (t == 0) {
        float mm = fmaxf(fmaxf(lg[0], lg[1]), fmaxf(lg[2], lg[3]));
        float e0 = __expf(lg[0] - mm), e1 = __expf(lg[1] - mm);
        float e2 = __expf(lg[2] - mm), e3 = __expf(lg[3] - mm);
        float inv = 1.f / (e0 + e1 + e2 + e3);
        g_mw[(size_t)b * 4 + 0] = e0 * inv;
        g_mw[(size_t)b * 4 + 1] = e1 * inv;
        g_mw[(size_t)b * 4 + 2] = e2 * inv;
        g_mw[(size_t)b * 4 + 3] = e3 * inv;
    }
}

// ---------------- students ----------------
__global__ void __launch_bounds__(128) student_kernel(const float* __restrict__ x,
                                                      const float* __restrict__ sw1,
                                                      const float* __restrict__ sw2,
                                                      const float* __restrict__ sb2,
                                                      float* __restrict__ out) {
    __shared__ float sb[512], w0[512], w1s[512], s2a[512], s2b[512];
    __shared__ float smw[4], sbias2[8];
    const int b = blockIdx.x, t = threadIdx.x;
    for (int i = t; i < 512; i += 128) {
        sb[i] = g_base[(size_t)b * 512 + i];
        int k = i >> 7, j = i & 127;
        w0[i] = sw1[((size_t)k * 258 + 0) * 128 + j];
        w1s[i] = sw1[((size_t)k * 258 + 1) * 128 + j];
        s2a[i] = sw2[i * 2 + 0];
        s2b[i] = sw2[i * 2 + 1];
    }
    if (t < 4) smw[t] = g_mw[(size_t)b * 4 + t];
    if (t < 8) sbias2[t] = sb2[t];
    __syncthreads();
    const float x0 = x[(size_t)b * 256 + t];
    const float x1 = x[(size_t)b * 256 + 128 + t];
    float o0 = 0.f, o1 = 0.f;
#pragma unroll
    for (int k = 0; k < 4; k++) {
        float a0 = 0.f, a1 = 0.f;
        for (int j = 0; j < 128; j++) {
            int idx = k * 128 + j;
            float hv = tanh_fast(fmaf(x1, w1s[idx], fmaf(x0, w0[idx], sb[idx])));
            a0 = fmaf(hv, s2a[idx], a0);
            a1 = fmaf(hv, s2b[idx], a1);
        }
        float wk = smw[k];
        o0 = fmaf(wk, a0 + sbias2[k * 2 + 0], o0);
        o1 = fmaf(wk, a1 + sbias2[k * 2 + 1], o1);
    }
    out[(size_t)b * 256 + t] = o0;
    out[(size_t)b * 256 + 128 + t] = o1;
}

// ---------------- launcher ----------------
extern "C" void kernel_launch(void* const* d_in, const int* in_sizes, int n_in,
                              void* d_out, int out_size) {
    const float* x    = (const float*)d_in[0];
    const int*   ts   = (const int*)d_in[1];
    const float* cond = (const float*)d_in[2];
    const float* t_w1 = (const float*)d_in[3];
    const float* t_b1 = (const float*)d_in[4];
    const float* t_w2 = (const float*)d_in[5];
    const float* t_b2 = (const float*)d_in[6];
    const float* c_w1 = (const float*)d_in[7];
    const float* c_b1 = (const float*)d_in[8];
    const float* c_w2 = (const float*)d_in[9];
    const float* c_b2 = (const float*)d_in[10];
    const float* wqkv = (const float*)d_in[11];
    const float* bqkv = (const float*)d_in[12];
    const float* wo   = (const float*)d_in[13];
    const float* bo   = (const float*)d_in[14];
    const float* ln1g = (const float*)d_in[15];
    const float* ln1b = (const float*)d_in[16];
    const float* ffw1 = (const float*)d_in[17];
    const float* ffb1 = (const float*)d_in[18];
    const float* ffw2 = (const float*)d_in[19];
    const float* ffb2 = (const float*)d_in[20];
    const float* ln2g = (const float*)d_in[21];
    const float* ln2b = (const float*)d_in[22];
    const float* mww1 = (const float*)d_in[23];
    const float* mwb1 = (const float*)d_in[24];
    const float* mww2 = (const float*)d_in[25];
    const float* mwb2 = (const float*)d_in[26];
    const float* sw1  = (const float*)d_in[27];
    const float* sb1  = (const float*)d_in[28];
    const float* sw2  = (const float*)d_in[29];
    const float* sb2  = (const float*)d_in[30];
    float* out = (float*)d_out;

    float *gh, *gqkv, *gcomb, *gbase;
    uint2 *ghp, *gap, *gcmb, *gw;
    cudaGetSymbolAddress((void**)&gh, g_h);
    cudaGetSymbolAddress((void**)&gqkv, g_qkv);
    cudaGetSymbolAddress((void**)&gcomb, g_comb);
    cudaGetSymbolAddress((void**)&gbase, g_base);
    cudaGetSymbolAddress((void**)&ghp, g_h_pack);
    cudaGetSymbolAddress((void**)&gap, g_attn_pack);
    cudaGetSymbolAddress((void**)&gcmb, g_comb_pack);
    cudaGetSymbolAddress((void**)&gw, g_wp);
    uint2* gfp = (uint2*)gqkv;   // ffn-hidden pack aliases qkv fp32 (disjoint liveness)
    uint2* gcp = gap;            // cond-hidden pack aliases attn pack (disjoint liveness)

    cudaFuncSetAttribute(attn_kernel, cudaFuncAttributeMaxDynamicSharedMemorySize, ATTN_SMEM);
    cudaFuncSetAttribute(tgemm<0>, cudaFuncAttributeMaxDynamicSharedMemorySize, TG_SMEM);
    cudaFuncSetAttribute(tgemm<1>, cudaFuncAttributeMaxDynamicSharedMemorySize, TG_SMEM);
    cudaFuncSetAttribute(tgemm<2>, cudaFuncAttributeMaxDynamicSharedMemorySize, TG_SMEM);
    cudaFuncSetAttribute(tgemm<3>, cudaFuncAttributeMaxDynamicSharedMemorySize, TG_SMEM);

    // pack all weights (tiny)
    packw<<<96, 256>>>(wqkv, gw + OFF_QKV0, 128, 384);
    packw<<<96, 256>>>(wqkv + 49152, gw + OFF_QKV1, 128, 384);
    packw<<<32, 256>>>(wo, gw + OFF_WO0, 128, 128);
    packw<<<32, 256>>>(wo + 16384, gw + OFF_WO1, 128, 128);
    packw<<<64, 256>>>(ffw1, gw + OFF_FF10, 128, 256);
    packw<<<64, 256>>>(ffw1 + 32768, gw + OFF_FF11, 128, 256);
    packw<<<64, 256>>>(ffw2, gw + OFF_FF20, 256, 128);
    packw<<<64, 256>>>(ffw2 + 32768, gw + OFF_FF21, 256, 128);
    packw<<<16, 256>>>(c_w2, gw + OFF_CW2, 64, 128);
    packsw1<<<256, 256>>>(sw1, gw + OFF_SW1);

    time_kernel<<<B_, 256>>>(ts, t_w1, t_b1, t_w2, t_b2);
    condh1_kernel<<<MROWS / 32, 256>>>(cond, c_w1, c_b1, gcp);
    // cond layer2: silu -> g_h (fp32) + g_h_pack
    tgemm<3><<<dim3(1, MROWS / 128), 128, TG_SMEM>>>(gcp, gw + OFF_CW2, 64, c_b2,
                                                     nullptr, nullptr, nullptr,
                                                     gh, 128, ghp, 64);
    const size_t qkvoff[2] = {OFF_QKV0, OFF_QKV1};
    const size_t wooff[2] = {OFF_WO0, OFF_WO1};
    const size_t f1off[2] = {OFF_FF10, OFF_FF11};
    const size_t f2off[2] = {OFF_FF20, OFF_FF21};
    for (int l = 0; l < 2; l++) {
        // qkv (fp32 out only); ffn pack (same region) is dead here
        tgemm<0><<<dim3(3, MROWS / 128), 128, TG_SMEM>>>(ghp, gw + qkvoff[l], 128,
                                                         bqkv + l * 384, nullptr, nullptr,
                                                         nullptr, gqkv, 384, nullptr, 0);
        attn_kernel<<<B_ * 4, 128, ATTN_SMEM>>>();   // reads qkv, writes attn_pack
        // o-proj + res + LN -> g_h + g_h_pack
        tgemm<2><<<dim3(1, MROWS / 128), 128, TG_SMEM>>>(gap, gw + wooff[l], 128,
                                                         bo + l * 128, gh, ln1g + l * 128,
                                                         ln1b + l * 128, gh, 128, ghp, 64);
        // ffn1 relu -> pack only (into dead qkv region)
        tgemm<1><<<dim3(2, MROWS / 128), 128, TG_SMEM>>>(ghp, gw + f1off[l], 128,
                                                         ffb1 + l * 256, nullptr, nullptr,
                                                         nullptr, nullptr, 0, gfp, 128);
        // ffn2 + res + LN -> g_h + g_h_pack
        tgemm<2><<<dim3(1, MROWS / 128), 128, TG_SMEM>>>(gfp, gw + f2off[l], 256,
                                                         ffb2 + l * 128, gh, ln2g + l * 128,
                                                         ln2b + l * 128, gh, 128, ghp, 64);
    }
    pool_kernel<<<B_, 128>>>();
    mw_kernel<<<B_, 128>>>(mww1, mwb1, mww2, mwb2);
    // student base: comb_pack [4096,256] @ sw1fold -> g_base fp32
    tgemm<0><<<dim3(4, B_ / 128), 128, TG_SMEM>>>(gcmb, gw + OFF_SW1, 256, sb1,
                                                  nullptr, nullptr, nullptr,
                                                  gbase, 512, nullptr, 0);
    student_kernel<<<B_, 128>>>(x, sw1, sw2, sb2, out);
}

// round 13
// speedup vs baseline: 1.8167x; 1.4881x over previous
#include <cuda_runtime.h>
#include <math.h>
#include <stdint.h>

#define B_    4096
#define MROWS (B_ * 128)   // 524288

// ---------------- global scratch (aliased; ~1.54GB total) ----------------
__device__ float g_h[(size_t)MROWS * 128];      // fp32 activations (residual path)
__device__ float g_qkv[(size_t)MROWS * 384];    // ALIAS: qkv_pack [row][192] uint2 / ffn_pack [row][128] uint2
__device__ float g_comb[(size_t)B_ * 256];
__device__ float g_mw[(size_t)B_ * 4];
__device__ float g_base[(size_t)B_ * 512];
__device__ uint2 g_h_pack[(size_t)MROWS * 64];
__device__ uint2 g_attn_pack[(size_t)MROWS * 64];  // ALIAS: ch1_pack
__device__ uint2 g_comb_pack[(size_t)B_ * 128];
__device__ uint2 g_wp[200704];

#define OFF_QKV0 0
#define OFF_QKV1 24576
#define OFF_WO0  49152
#define OFF_WO1  57344
#define OFF_FF10 65536
#define OFF_FF11 81920
#define OFF_FF20 98304
#define OFF_FF21 114688
#define OFF_CW2  131072
#define OFF_SW1  135168

typedef unsigned long long u64t;

__device__ __forceinline__ float siluf(float x) { return x / (1.f + __expf(-x)); }
__device__ __forceinline__ float tanh_fast(float x) { return 1.f - 2.f / (__expf(2.f * x) + 1.f); }
__device__ __forceinline__ uint32_t smem_u32(const void* p) {
    uint32_t a;
    asm("{ .reg .u64 t; cvta.to.shared.u64 t, %1; cvt.u32.u64 %0, t; }" : "=r"(a) : "l"(p));
    return a;
}

// pack two fp32 (v0 = even idx, v1 = odd idx) into {hi bf16x2, lo bf16x2}
__device__ __forceinline__ uint2 pack_bf16_pair(float v0, float v1) {
    uint32_t hi;
    asm("cvt.rn.bf16x2.f32 %0, %1, %2;" : "=r"(hi) : "f"(v1), "f"(v0));
    float b0 = __uint_as_float(hi << 16);
    float b1 = __uint_as_float(hi & 0xffff0000u);
    uint32_t lo;
    asm("cvt.rn.bf16x2.f32 %0, %1, %2;" : "=r"(lo) : "f"(v1 - b1), "f"(v0 - b0));
    return make_uint2(hi, lo);
}

// ---- cp.async ----
__device__ __forceinline__ void cp16(uint32_t dst, const void* src) {
    asm volatile("cp.async.ca.shared.global [%0], [%1], 16;" :: "r"(dst), "l"(src));
}
__device__ __forceinline__ void cp_commit() { asm volatile("cp.async.commit_group;" ::: "memory"); }
template <int N>
__device__ __forceinline__ void cp_wait() { asm volatile("cp.async.wait_group %0;" :: "n"(N) : "memory"); }

// ---- bf16 mma.sync m16n8k16 ----
__device__ __forceinline__ void mma16(float* c, const uint32_t* a, uint32_t b0, uint32_t b1) {
    asm volatile(
        "mma.sync.aligned.m16n8k16.row.col.f32.bf16.bf16.f32 "
        "{%0,%1,%2,%3}, {%4,%5,%6,%7}, {%8,%9}, {%0,%1,%2,%3};"
        : "+f"(c[0]), "+f"(c[1]), "+f"(c[2]), "+f"(c[3])
        : "r"(a[0]), "r"(a[1]), "r"(a[2]), "r"(a[3]), "r"(b0), "r"(b1));
}

// ---------------- weight pre-pack ----------------
__global__ void __launch_bounds__(256) packw(const float* __restrict__ W, uint2* __restrict__ dst,
                                             int K, int N) {
    int kp2 = K >> 1;
    int idx = blockIdx.x * 256 + threadIdx.x;
    if (idx >= N * kp2) return;
    int n = idx / kp2, kp = idx - n * kp2;
    int chunk = n >> 7, nn = n & 127;
    dst[((size_t)chunk * 128 + nn) * kp2 + kp] =
        pack_bf16_pair(W[(size_t)(2 * kp) * N + n], W[(size_t)(2 * kp + 1) * N + n]);
}
__global__ void __launch_bounds__(256) packsw1(const float* __restrict__ sw1, uint2* __restrict__ dst) {
    int idx = blockIdx.x * 256 + threadIdx.x;   // < 512*128
    if (idx >= 512 * 128) return;
    int n = idx / 128, kp = idx - (idx / 128) * 128;
    int chunk = n >> 7, nn = n & 127;
    float v0 = sw1[((size_t)(n >> 7) * 258 + 2 + 2 * kp) * 128 + nn];
    float v1 = sw1[((size_t)(n >> 7) * 258 + 2 + 2 * kp + 1) * 128 + nn];
    dst[((size_t)chunk * 128 + nn) * 128 + kp] = pack_bf16_pair(v0, v1);
}

// ---------------- bf16 2-term tensor GEMM ----------------
// MODE: 0 bias fp32-only, 1 relu pack-only, 2 res+LN both, 3 silu both, 5 bias pack-only
#define RS 20
#define TBUF 20480
#define TG_SMEM (4 * TBUF)
template <int MODE>
__global__ void __launch_bounds__(128, 2) tgemm(const uint2* __restrict__ Apack,
                                                const uint2* __restrict__ Bpack,
                                                int Ktot,
                                                const float* __restrict__ bias,
                                                const float* __restrict__ res,
                                                const float* __restrict__ gma,
                                                const float* __restrict__ bta,
                                                float* __restrict__ C, int ldc,
                                                uint2* __restrict__ Cpack, int ldcp) {
    extern __shared__ char dsm[];
    const uint32_t sbase = smem_u32(dsm);
    const int t = threadIdx.x;
    const int w = t >> 5, lane = t & 31;
    const int g = lane >> 2, t4 = lane & 3;
    const int bn = blockIdx.x * 128, bm = blockIdx.y * 128;
    const int wrow = w * 32;
    const int kpTot = Ktot >> 1;

    float acc0[16][4], acc1[16][4];
#pragma unroll
    for (int j = 0; j < 16; j++)
#pragma unroll
        for (int q = 0; q < 4; q++) { acc0[j][q] = 0.f; acc1[j][q] = 0.f; }

    const int P = Ktot >> 5;
    const uint2* Bbase = Bpack + (size_t)blockIdx.x * 128 * kpTot;
    const int srow = t >> 3;
    const int sj = t & 7;

#pragma unroll
    for (int i = 0; i < 8; i++) {
        int row = srow + i * 16;
        cp16(sbase + (uint32_t)(row * RS * 8 + sj * 16),
             Apack + (size_t)(bm + row) * kpTot + sj * 2);
        cp16(sbase + (uint32_t)(2 * TBUF + row * RS * 8 + sj * 16),
             Bbase + (size_t)row * kpTot + sj * 2);
    }
    cp_commit();

    for (int p = 0; p < P; p++) {
        const bool more = (p + 1 < P);
        if (more) {
            const int buf = (p + 1) & 1;
            const int kpo = (p + 1) * 16;
#pragma unroll
            for (int i = 0; i < 8; i++) {
                int row = srow + i * 16;
                cp16(sbase + (uint32_t)(buf * TBUF + row * RS * 8 + sj * 16),
                     Apack + (size_t)(bm + row) * kpTot + kpo + sj * 2);
                cp16(sbase + (uint32_t)(2 * TBUF + buf * TBUF + row * RS * 8 + sj * 16),
                     Bbase + (size_t)row * kpTot + kpo + sj * 2);
            }
            cp_commit();
            cp_wait<1>();
        } else {
            cp_wait<0>();
        }
        __syncthreads();

        const uint2* As = (const uint2*)(dsm + (p & 1) * TBUF);
        const uint2* Bs = (const uint2*)(dsm + 2 * TBUF + (p & 1) * TBUF);
#pragma unroll
        for (int h2 = 0; h2 < 2; h2++) {
            const int kb = h2 * 8;
            const int r = wrow + g;
            uint32_t a0h[4], a0l[4], a1h[4], a1l[4];
            uint2 q;
            q = As[(r) * RS + kb + t4];          a0h[0] = q.x; a0l[0] = q.y;
            q = As[(r + 8) * RS + kb + t4];      a0h[1] = q.x; a0l[1] = q.y;
            q = As[(r) * RS + kb + t4 + 4];      a0h[2] = q.x; a0l[2] = q.y;
            q = As[(r + 8) * RS + kb + t4 + 4];  a0h[3] = q.x; a0l[3] = q.y;
            q = As[(r + 16) * RS + kb + t4];     a1h[0] = q.x; a1l[0] = q.y;
            q = As[(r + 24) * RS + kb + t4];     a1h[1] = q.x; a1l[1] = q.y;
            q = As[(r + 16) * RS + kb + t4 + 4]; a1h[2] = q.x; a1l[2] = q.y;
            q = As[(r + 24) * RS + kb + t4 + 4]; a1h[3] = q.x; a1l[3] = q.y;
#pragma unroll
            for (int j = 0; j < 16; j++) {
                uint2 b0 = Bs[(j * 8 + g) * RS + kb + t4];
                uint2 b1 = Bs[(j * 8 + g) * RS + kb + t4 + 4];
                mma16(acc0[j], a0h, b0.x, b1.x);
                mma16(acc0[j], a0l, b0.x, b1.x);
                mma16(acc0[j], a0h, b0.y, b1.y);
                mma16(acc1[j], a1h, b0.x, b1.x);
                mma16(acc1[j], a1l, b0.x, b1.x);
                mma16(acc1[j], a1h, b0.y, b1.y);
            }
        }
        __syncthreads();
    }

    float2 bias2[16];
#pragma unroll
    for (int j = 0; j < 16; j++) bias2[j] = *(const float2*)(bias + bn + j * 8 + 2 * t4);

    if (MODE == 2) {
#pragma unroll
        for (int i = 0; i < 2; i++) {
            float (*ac)[4] = i ? acc1 : acc0;
#pragma unroll
            for (int h = 0; h < 2; h++) {
                const int row = bm + wrow + i * 16 + h * 8 + g;
                const float* rp = res + (size_t)row * 128 + 2 * t4;
                float sum = 0.f;
#pragma unroll
                for (int j = 0; j < 16; j++) {
                    float2 rv = *(const float2*)(rp + j * 8);
                    float v0 = ac[j][2 * h] + bias2[j].x + rv.x;
                    float v1 = ac[j][2 * h + 1] + bias2[j].y + rv.y;
                    ac[j][2 * h] = v0;
                    ac[j][2 * h + 1] = v1;
                    sum += v0 + v1;
                }
                sum += __shfl_xor_sync(0xffffffffu, sum, 1);
                sum += __shfl_xor_sync(0xffffffffu, sum, 2);
                const float mean = sum * (1.f / 128.f);
                float var = 0.f;
#pragma unroll
                for (int j = 0; j < 16; j++) {
                    float v0 = ac[j][2 * h] - mean;
                    float v1 = ac[j][2 * h + 1] - mean;
                    ac[j][2 * h] = v0;
                    ac[j][2 * h + 1] = v1;
                    var += v0 * v0 + v1 * v1;
                }
                var += __shfl_xor_sync(0xffffffffu, var, 1);
                var += __shfl_xor_sync(0xffffffffu, var, 2);
                const float rs = rsqrtf(var * (1.f / 128.f) + 1e-5f);
                float* cp = C + (size_t)row * 128 + 2 * t4;
                uint2* pp = Cpack + (size_t)row * ldcp + t4;
#pragma unroll
                for (int j = 0; j < 16; j++) {
                    float2 gv = *(const float2*)(gma + j * 8 + 2 * t4);
                    float2 tv = *(const float2*)(bta + j * 8 + 2 * t4);
                    float2 o;
                    o.x = fmaf(gv.x, ac[j][2 * h] * rs, tv.x);
                    o.y = fmaf(gv.y, ac[j][2 * h + 1] * rs, tv.y);
                    *(float2*)(cp + j * 8) = o;
                    pp[4 * j] = pack_bf16_pair(o.x, o.y);
                }
            }
        }
    } else {
#pragma unroll
        for (int i = 0; i < 2; i++) {
            float (*ac)[4] = i ? acc1 : acc0;
#pragma unroll
            for (int h = 0; h < 2; h++) {
                const int row = bm + wrow + i * 16 + h * 8 + g;
                float* cp = (MODE == 0 || MODE == 3) ? (C + (size_t)row * ldc + bn + 2 * t4) : nullptr;
                uint2* pp = (MODE != 0) ? (Cpack + (size_t)row * ldcp + (bn >> 1) + t4) : nullptr;
#pragma unroll
                for (int j = 0; j < 16; j++) {
                    float2 o;
                    o.x = ac[j][2 * h] + bias2[j].x;
                    o.y = ac[j][2 * h + 1] + bias2[j].y;
                    if (MODE == 1) { o.x = fmaxf(o.x, 0.f); o.y = fmaxf(o.y, 0.f); }
                    if (MODE == 3) { o.x = siluf(o.x); o.y = siluf(o.y); }
                    if (MODE == 0 || MODE == 3) *(float2*)(cp + j * 8) = o;
                    if (MODE != 0) pp[4 * j] = pack_bf16_pair(o.x, o.y);
                }
            }
        }
    }
}

// ---------------- time embedding ----------------
__global__ void __launch_bounds__(256) time_kernel(const int* __restrict__ ts,
                                                   const float* __restrict__ w1,
                                                   const float* __restrict__ b1,
                                                   const float* __restrict__ w2,
                                                   const float* __restrict__ b2) {
    __shared__ float te[128];
    __shared__ float hid[256];
    __shared__ float tout[128];
    const int b = blockIdx.x, t = threadIdx.x;
    const float tf = (float)ts[b];
    if (t < 128) {
        int i = t & 63;
        float freq = expf(-0.14391156831212787f * (float)i);
        float arg = tf * freq;
        te[t] = (t < 64) ? cosf(arg) : sinf(arg);
    }
    __syncthreads();
    float a = b1[t];
    for (int i = 0; i < 128; i++) a = fmaf(te[i], w1[i * 256 + t], a);
    hid[t] = siluf(a);
    __syncthreads();
    if (t < 128) {
        float a2 = b2[t];
        for (int i = 0; i < 256; i++) a2 = fmaf(hid[i], w2[i * 128 + t], a2);
        g_comb[(size_t)b * 256 + t] = a2;
        tout[t] = a2;
    }
    __syncthreads();
    if (t < 64) g_comb_pack[(size_t)b * 128 + t] = pack_bf16_pair(tout[2 * t], tout[2 * t + 1]);
}

// ---------------- cond layer1 -> packed ----------------
__global__ void __launch_bounds__(256) condh1_kernel(const float* __restrict__ cond,
                                                     const float* __restrict__ w1,
                                                     const float* __restrict__ b1,
                                                     uint2* __restrict__ outp) {
    const size_t row = (size_t)blockIdx.x * 32 + (threadIdx.x >> 3);
    const int dg = threadIdx.x & 7;
    const float* cp = cond + row * 6;
    float c0 = cp[0], c1 = cp[1], c2 = cp[2], c3 = cp[3], c4 = cp[4], c5 = cp[5];
    float o[8];
#pragma unroll
    for (int j = 0; j < 8; j++) {
        int dd = dg * 8 + j;
        float a = b1[dd];
        a = fmaf(c0, w1[0 * 64 + dd], a);
        a = fmaf(c1, w1[1 * 64 + dd], a);
        a = fmaf(c2, w1[2 * 64 + dd], a);
        a = fmaf(c3, w1[3 * 64 + dd], a);
        a = fmaf(c4, w1[4 * 64 + dd], a);
        a = fmaf(c5, w1[5 * 64 + dd], a);
        o[j] = siluf(a);
    }
#pragma unroll
    for (int i = 0; i < 4; i++)
        outp[row * 32 + dg * 4 + i] = pack_bf16_pair(o[2 * i], o[2 * i + 1]);
}

// ---------------- attention: bf16 MMA, per (b,head) CTA ----------------
// smem: Qp[128][20] | Kp[128][20] | Vp[128][20] (uint2, packed pairs over dims)
//       Vt[32][66] (uint2, packed pairs over keys)
#define ATTN_SMEM (3 * 20480 + 32 * 66 * 8)   // 78336
__global__ void __launch_bounds__(128, 2) attn_kernel(const uint2* __restrict__ qkvp) {
    extern __shared__ char sm[];
    uint2* Qp = (uint2*)sm;
    uint2* Kp = (uint2*)(sm + 20480);
    uint2* Vp = (uint2*)(sm + 40960);
    uint2* Vt = (uint2*)(sm + 61440);
    const uint32_t sb = smem_u32(sm);
    const int b = blockIdx.x >> 2, hd = blockIdx.x & 3;
    const int t = threadIdx.x, w = t >> 5, lane = t & 31;
    const int g = lane >> 2, t4 = lane & 3;
    const int wrow = w * 32;
    const int srow = t >> 3, sj = t & 7;
    const uint2* base = qkvp + (size_t)(b * 128) * 192;

    // stage Q, K, V packed tiles (coalesced: 8 lanes per row)
#pragma unroll
    for (int i = 0; i < 8; i++) {
        int row = srow + i * 16;
        const uint2* rp = base + (size_t)row * 192;
        cp16(sb + (uint32_t)((row * RS + sj * 2) * 8), rp + hd * 16 + sj * 2);
        cp16(sb + 20480u + (uint32_t)((row * RS + sj * 2) * 8), rp + 64 + hd * 16 + sj * 2);
        cp16(sb + 40960u + (uint32_t)((row * RS + sj * 2) * 8), rp + 128 + hd * 16 + sj * 2);
    }
    cp_commit();
    cp_wait<0>();
    __syncthreads();

    // build Vt[d][kp] = pack(V[2kp][d], V[2kp+1][d])
    for (int e = t; e < 32 * 64; e += 128) {
        int d = e >> 6, kp = e & 63;
        uint2 p0 = Vp[(2 * kp) * RS + (d >> 1)];
        uint2 p1 = Vp[(2 * kp + 1) * RS + (d >> 1)];
        float v0, v1;
        if (d & 1) {
            v0 = __uint_as_float(p0.x & 0xffff0000u) + __uint_as_float(p0.y & 0xffff0000u);
            v1 = __uint_as_float(p1.x & 0xffff0000u) + __uint_as_float(p1.y & 0xffff0000u);
        } else {
            v0 = __uint_as_float(p0.x << 16) + __uint_as_float(p0.y << 16);
            v1 = __uint_as_float(p1.x << 16) + __uint_as_float(p1.y << 16);
        }
        Vt[d * 66 + kp] = pack_bf16_pair(v0, v1);
    }
    __syncthreads();

    const float cs = 0.17677669529663687f;   // 1/sqrt(32)

#pragma unroll
    for (int tile = 0; tile < 2; tile++) {
        float acc[16][4];
#pragma unroll
        for (int j = 0; j < 16; j++)
#pragma unroll
            for (int q = 0; q < 4; q++) acc[j][q] = 0.f;
        const int r = wrow + tile * 16 + g;

        // S = Q @ K^T (3-term bf16)
#pragma unroll
        for (int h2 = 0; h2 < 2; h2++) {
            const int kb = h2 * 8;
            uint32_t ah[4], al[4];
            uint2 q;
            q = Qp[r * RS + kb + t4];           ah[0] = q.x; al[0] = q.y;
            q = Qp[(r + 8) * RS + kb + t4];     ah[1] = q.x; al[1] = q.y;
            q = Qp[r * RS + kb + t4 + 4];       ah[2] = q.x; al[2] = q.y;
            q = Qp[(r + 8) * RS + kb + t4 + 4]; ah[3] = q.x; al[3] = q.y;
#pragma unroll
            for (int j = 0; j < 16; j++) {
                uint2 b0 = Kp[(j * 8 + g) * RS + kb + t4];
                uint2 b1 = Kp[(j * 8 + g) * RS + kb + t4 + 4];
                mma16(acc[j], ah, b0.x, b1.x);
                mma16(acc[j], al, b0.x, b1.x);
                mma16(acc[j], ah, b0.y, b1.y);
            }
        }

        // softmax: rows r (regs 0,1) and r+8 (regs 2,3); cols reduced over quad
        float m0 = -1e30f, m1 = -1e30f;
#pragma unroll
        for (int j = 0; j < 16; j++) {
            m0 = fmaxf(m0, fmaxf(acc[j][0], acc[j][1]));
            m1 = fmaxf(m1, fmaxf(acc[j][2], acc[j][3]));
        }
        m0 = fmaxf(m0, __shfl_xor_sync(0xffffffffu, m0, 1));
        m0 = fmaxf(m0, __shfl_xor_sync(0xffffffffu, m0, 2));
        m1 = fmaxf(m1, __shfl_xor_sync(0xffffffffu, m1, 1));
        m1 = fmaxf(m1, __shfl_xor_sync(0xffffffffu, m1, 2));
        float l0 = 0.f, l1 = 0.f;
#pragma unroll
        for (int j = 0; j < 16; j++) {
            acc[j][0] = __expf((acc[j][0] - m0) * cs);
            acc[j][1] = __expf((acc[j][1] - m0) * cs);
            acc[j][2] = __expf((acc[j][2] - m1) * cs);
            acc[j][3] = __expf((acc[j][3] - m1) * cs);
            l0 += acc[j][0] + acc[j][1];
            l1 += acc[j][2] + acc[j][3];
        }
        l0 += __shfl_xor_sync(0xffffffffu, l0, 1);
        l0 += __shfl_xor_sync(0xffffffffu, l0, 2);
        l1 += __shfl_xor_sync(0xffffffffu, l1, 1);
        l1 += __shfl_xor_sync(0xffffffffu, l1, 2);
        const float li0 = 1.f / l0, li1 = 1.f / l1;

        // O = P @ V : P C-frags -> A-frags in registers (hi + lo), 3-term
        float o[4][4];
#pragma unroll
        for (int j = 0; j < 4; j++)
#pragma unroll
            for (int q = 0; q < 4; q++) o[j][q] = 0.f;
#pragma unroll
        for (int kc = 0; kc < 8; kc++) {
            uint32_t ph[4], pl[4];
            uint2 u;
            u = pack_bf16_pair(acc[2 * kc][0], acc[2 * kc][1]);         ph[0] = u.x; pl[0] = u.y;
            u = pack_bf16_pair(acc[2 * kc][2], acc[2 * kc][3]);         ph[1] = u.x; pl[1] = u.y;
            u = pack_bf16_pair(acc[2 * kc + 1][0], acc[2 * kc + 1][1]); ph[2] = u.x; pl[2] = u.y;
            u = pack_bf16_pair(acc[2 * kc + 1][2], acc[2 * kc + 1][3]); ph[3] = u.x; pl[3] = u.y;
#pragma unroll
            for (int j = 0; j < 4; j++) {
                uint2 b0 = Vt[(j * 8 + g) * 66 + kc * 8 + t4];
                uint2 b1 = Vt[(j * 8 + g) * 66 + kc * 8 + t4 + 4];
                mma16(o[j], ph, b0.x, b1.x);
                mma16(o[j], pl, b0.x, b1.x);
                mma16(o[j], ph, b0.y, b1.y);
            }
        }

        const int row0 = b * 128 + r;
        uint2* p0 = g_attn_pack + (size_t)row0 * 64 + hd * 16 + t4;
        uint2* p1 = g_attn_pack + (size_t)(row0 + 8) * 64 + hd * 16 + t4;
#pragma unroll
        for (int j = 0; j < 4; j++) {
            p0[j * 4] = pack_bf16_pair(o[j][0] * li0, o[j][1] * li0);
            p1[j * 4] = pack_bf16_pair(o[j][2] * li1, o[j][3] * li1);
        }
    }
}

// ---------------- mean pool ----------------
__global__ void __launch_bounds__(128) pool_kernel() {
    __shared__ float buf[128];
    const int b = blockIdx.x, d = threadIdx.x;
    const float* p = g_h + (size_t)b * 128 * 128 + d;
    float s = 0.f;
    for (int j = 0; j < 128; j++) s += p[j * 128];
    s *= (1.f / 128.f);
    g_comb[(size_t)b * 256 + 128 + d] = s;
    buf[d] = s;
    __syncthreads();
    if (d < 64) g_comb_pack[(size_t)b * 128 + 64 + d] = pack_bf16_pair(buf[2 * d], buf[2 * d + 1]);
}

// ---------------- mixture weights ----------------
__global__ void __launch_bounds__(128) mw_kernel(const float* __restrict__ w1,
                                                 const float* __restrict__ b1,
                                                 const float* __restrict__ w2,
                                                 const float* __restrict__ b2) {
    __shared__ float scm[256];
    __shared__ float hid[128];
    __shared__ float lg[4];
    const int b = blockIdx.x, t = threadIdx.x;
    scm[t] = g_comb[(size_t)b * 256 + t];
    scm[128 + t] = g_comb[(size_t)b * 256 + 128 + t];
    __syncthreads();
    float a = b1[t];
    for (int i = 0; i < 256; i++) a = fmaf(scm[i], w1[i * 128 + t], a);
    hid[t] = siluf(a);
    __syncthreads();
    if (t < 4) {
        float a2 = b2[t];
        for (int j = 0; j < 128; j++) a2 = fmaf(hid[j], w2[j * 4 + t], a2);
        lg[t] = a2;
    }
    __syncthreads();
    if (t == 0) {
        float mm = fmaxf(fmaxf(lg[0], lg[1]), fmaxf(lg[2], lg[3]));
        float e0 = __expf(lg[0] - mm), e1 = __expf(lg[1] - mm);
        float e2 = __expf(lg[2] - mm), e3 = __expf(lg[3] - mm);
        float inv = 1.f / (e0 + e1 + e2 + e3);
        g_mw[(size_t)b * 4 + 0] = e0 * inv;
        g_mw[(size_t)b * 4 + 1] = e1 * inv;
        g_mw[(size_t)b * 4 + 2] = e2 * inv;
        g_mw[(size_t)b * 4 + 3] = e3 * inv;
    }
}

// ---------------- students ----------------
__global__ void __launch_bounds__(128) student_kernel(const float* __restrict__ x,
                                                      const float* __restrict__ sw1,
                                                      const float* __restrict__ sw2,
                                                      const float* __restrict__ sb2,
                                                      float* __restrict__ out) {
    __shared__ float sb[512], w0[512], w1s[512], s2a[512], s2b[512];
    __shared__ float smw[4], sbias2[8];
    const int b = blockIdx.x, t = threadIdx.x;
    for (int i = t; i < 512; i += 128) {
        sb[i] = g_base[(size_t)b * 512 + i];
        int k = i >> 7, j = i & 127;
        w0[i] = sw1[((size_t)k * 258 + 0) * 128 + j];
        w1s[i] = sw1[((size_t)k * 258 + 1) * 128 + j];
        s2a[i] = sw2[i * 2 + 0];
        s2b[i] = sw2[i * 2 + 1];
    }
    if (t < 4) smw[t] = g_mw[(size_t)b * 4 + t];
    if (t < 8) sbias2[t] = sb2[t];
    __syncthreads();
    const float x0 = x[(size_t)b * 256 + t];
    const float x1 = x[(size_t)b * 256 + 128 + t];
    float o0 = 0.f, o1 = 0.f;
#pragma unroll
    for (int k = 0; k < 4; k++) {
        float a0 = 0.f, a1 = 0.f;
        for (int j = 0; j < 128; j++) {
            int idx = k * 128 + j;
            float hv = tanh_fast(fmaf(x1, w1s[idx], fmaf(x0, w0[idx], sb[idx])));
            a0 = fmaf(hv, s2a[idx], a0);
            a1 = fmaf(hv, s2b[idx], a1);
        }
        float wk = smw[k];
        o0 = fmaf(wk, a0 + sbias2[k * 2 + 0], o0);
        o1 = fmaf(wk, a1 + sbias2[k * 2 + 1], o1);
    }
    out[(size_t)b * 256 + t] = o0;
    out[(size_t)b * 256 + 128 + t] = o1;
}

// ---------------- launcher ----------------
extern "C" void kernel_launch(void* const* d_in, const int* in_sizes, int n_in,
                              void* d_out, int out_size) {
    const float* x    = (const float*)d_in[0];
    const int*   ts   = (const int*)d_in[1];
    const float* cond = (const float*)d_in[2];
    const float* t_w1 = (const float*)d_in[3];
    const float* t_b1 = (const float*)d_in[4];
    const float* t_w2 = (const float*)d_in[5];
    const float* t_b2 = (const float*)d_in[6];
    const float* c_w1 = (const float*)d_in[7];
    const float* c_b1 = (const float*)d_in[8];
    const float* c_w2 = (const float*)d_in[9];
    const float* c_b2 = (const float*)d_in[10];
    const float* wqkv = (const float*)d_in[11];
    const float* bqkv = (const float*)d_in[12];
    const float* wo   = (const float*)d_in[13];
    const float* bo   = (const float*)d_in[14];
    const float* ln1g = (const float*)d_in[15];
    const float* ln1b = (const float*)d_in[16];
    const float* ffw1 = (const float*)d_in[17];
    const float* ffb1 = (const float*)d_in[18];
    const float* ffw2 = (const float*)d_in[19];
    const float* ffb2 = (const float*)d_in[20];
    const float* ln2g = (const float*)d_in[21];
    const float* ln2b = (const float*)d_in[22];
    const float* mww1 = (const float*)d_in[23];
    const float* mwb1 = (const float*)d_in[24];
    const float* mww2 = (const float*)d_in[25];
    const float* mwb2 = (const float*)d_in[26];
    const float* sw1  = (const float*)d_in[27];
    const float* sb1  = (const float*)d_in[28];
    const float* sw2  = (const float*)d_in[29];
    const float* sb2  = (const float*)d_in[30];
    float* out = (float*)d_out;

    float *gh, *gqkv, *gcomb, *gbase;
    uint2 *ghp, *gap, *gcmb, *gw;
    cudaGetSymbolAddress((void**)&gh, g_h);
    cudaGetSymbolAddress((void**)&gqkv, g_qkv);
    cudaGetSymbolAddress((void**)&gcomb, g_comb);
    cudaGetSymbolAddress((void**)&gbase, g_base);
    cudaGetSymbolAddress((void**)&ghp, g_h_pack);
    cudaGetSymbolAddress((void**)&gap, g_attn_pack);
    cudaGetSymbolAddress((void**)&gcmb, g_comb_pack);
    cudaGetSymbolAddress((void**)&gw, g_wp);
    uint2* gqp = (uint2*)gqkv;   // qkv pack [row][192]  (aliases ffn pack region)
    uint2* gfp = (uint2*)gqkv;   // ffn-hidden pack [row][128] (after attn consumed qkv pack)
    uint2* gcp = gap;            // cond-hidden pack aliases attn pack

    cudaFuncSetAttribute(attn_kernel, cudaFuncAttributeMaxDynamicSharedMemorySize, ATTN_SMEM);
    cudaFuncSetAttribute(tgemm<0>, cudaFuncAttributeMaxDynamicSharedMemorySize, TG_SMEM);
    cudaFuncSetAttribute(tgemm<1>, cudaFuncAttributeMaxDynamicSharedMemorySize, TG_SMEM);
    cudaFuncSetAttribute(tgemm<2>, cudaFuncAttributeMaxDynamicSharedMemorySize, TG_SMEM);
    cudaFuncSetAttribute(tgemm<3>, cudaFuncAttributeMaxDynamicSharedMemorySize, TG_SMEM);
    cudaFuncSetAttribute(tgemm<5>, cudaFuncAttributeMaxDynamicSharedMemorySize, TG_SMEM);

    packw<<<96, 256>>>(wqkv, gw + OFF_QKV0, 128, 384);
    packw<<<96, 256>>>(wqkv + 49152, gw + OFF_QKV1, 128, 384);
    packw<<<32, 256>>>(wo, gw + OFF_WO0, 128, 128);
    packw<<<32, 256>>>(wo + 16384, gw + OFF_WO1, 128, 128);
    packw<<<64, 256>>>(ffw1, gw + OFF_FF10, 128, 256);
    packw<<<64, 256>>>(ffw1 + 32768, gw + OFF_FF11, 128, 256);
    packw<<<64, 256>>>(ffw2, gw + OFF_FF20, 256, 128);
    packw<<<64, 256>>>(ffw2 + 32768, gw + OFF_FF21, 256, 128);
    packw<<<16, 256>>>(c_w2, gw + OFF_CW2, 64, 128);
    packsw1<<<256, 256>>>(sw1, gw + OFF_SW1);

    time_kernel<<<B_, 256>>>(ts, t_w1, t_b1, t_w2, t_b2);
    condh1_kernel<<<MROWS / 32, 256>>>(cond, c_w1, c_b1, gcp);
    // cond layer2: silu -> g_h fp32 + g_h_pack
    tgemm<3><<<dim3(1, MROWS / 128), 128, TG_SMEM>>>(gcp, gw + OFF_CW2, 64, c_b2,
                                                     nullptr, nullptr, nullptr,
                                                     gh, 128, ghp, 64);
    const size_t qkvoff[2] = {OFF_QKV0, OFF_QKV1};
    const size_t wooff[2] = {OFF_WO0, OFF_WO1};
    const size_t f1off[2] = {OFF_FF10, OFF_FF11};
    const size_t f2off[2] = {OFF_FF20, OFF_FF21};
    for (int l = 0; l < 2; l++) {
        // qkv: pack-only output [row][192]
        tgemm<5><<<dim3(3, MROWS / 128), 128, TG_SMEM>>>(ghp, gw + qkvoff[l], 128,
                                                         bqkv + l * 384, nullptr, nullptr,
                                                         nullptr, nullptr, 0, gqp, 192);
        attn_kernel<<<B_ * 4, 128, ATTN_SMEM>>>(gqp);
        // o-proj + res + LN -> g_h + g_h_pack
        tgemm<2><<<dim3(1, MROWS / 128), 128, TG_SMEM>>>(gap, gw + wooff[l], 128,
                                                         bo + l * 128, gh, ln1g + l * 128,
                                                         ln1b + l * 128, gh, 128, ghp, 64);
        // ffn1 relu -> pack only (into dead qkv-pack region)
        tgemm<1><<<dim3(2, MROWS / 128), 128, TG_SMEM>>>(ghp, gw + f1off[l], 128,
                                                         ffb1 + l * 256, nullptr, nullptr,
                                                         nullptr, nullptr, 0, gfp, 128);
        // ffn2 + res + LN -> g_h + g_h_pack
        tgemm<2><<<dim3(1, MROWS / 128), 128, TG_SMEM>>>(gfp, gw + f2off[l], 256,
                                                         ffb2 + l * 128, gh, ln2g + l * 128,
                                                         ln2b + l * 128, gh, 128, ghp, 64);
    }
    pool_kernel<<<B_, 128>>>();
    mw_kernel<<<B_, 128>>>(mww1, mwb1, mww2, mwb2);
    tgemm<0><<<dim3(4, B_ / 128), 128, TG_SMEM>>>(gcmb, gw + OFF_SW1, 256, sb1,
                                                  nullptr, nullptr, nullptr,
                                                  gbase, 512, nullptr, 0);
    student_kernel<<<B_, 128>>>(x, sw1, sw2, sb2, out);
}